// round 2
// baseline (speedup 1.0000x reference)
#include <cuda_runtime.h>
#include <cstdint>

// Problem constants (fixed by reference)
#define N_NODES 50000
#define E_EDGES 800000
#define E_TOT   850000   // E + N self loops
#define G_GRAPHS 64
#define C1 256           // HEADS*HID after layer 1
#define C2 64            // HID after layer 2
#define H1 4             // heads layer 1
#define NEG_SLOPE 0.2f

// ------------------------- device scratch (no allocs allowed) ---------------
__device__ float g_h1[N_NODES * C1];        // x @ W1
__device__ float g_out1[N_NODES * C1];      // layer1 aggregation -> elu(.. + b1)
__device__ float g_h2[N_NODES * C2];        // out1 @ W2
__device__ float g_out2[N_NODES * C2];      // layer2 aggregation -> elu(.. + b2)
__device__ float g_asrc1[N_NODES * H1];
__device__ float g_adst1[N_NODES * H1];
__device__ unsigned g_emax1[N_NODES * H1];  // order-encoded float max
__device__ float g_esum1[N_NODES * H1];
__device__ float g_asrc2[N_NODES];
__device__ float g_adst2[N_NODES];
__device__ unsigned g_emax2[N_NODES];
__device__ float g_esum2[N_NODES];
__device__ float g_w1e[E_TOT * H1];         // per-edge exp weights layer 1
__device__ float g_w2e[E_TOT];              // per-edge exp weights layer 2
__device__ float g_pool[G_GRAPHS * C2];
__device__ int   g_cnt[G_GRAPHS];
__device__ int   g_is64;                    // 1 if indices are int64, 0 if int32

// ---------------------- helpers ---------------------------------------------
__device__ __forceinline__ unsigned enc_f(float f) {
    unsigned u = __float_as_uint(f);
    return (u & 0x80000000u) ? ~u : (u | 0x80000000u);
}
__device__ __forceinline__ float dec_f(unsigned u) {
    unsigned b = (u & 0x80000000u) ? (u ^ 0x80000000u) : ~u;
    return __uint_as_float(b);
}
// Index accessor: dispatch on runtime-detected dtype of the index buffers.
__device__ __forceinline__ int idx_at(const void* __restrict__ p, int i) {
    if (g_is64) return (int)((const long long*)p)[i];
    return ((const int*)p)[i];
}

// ---------------------- dtype detection -------------------------------------
// If the buffer holds int32 indices, interpreting pairs as int64 yields
// lo + hi*2^32 >= 2^32 whenever hi != 0, which happens within a few samples.
__global__ void detect_kernel(const void* __restrict__ ei) {
    const long long* p = (const long long*)ei;
    int ok64 = 1;
    for (int i = 0; i < 64; i++) {
        long long v = p[i];
        if (v < 0 || v >= N_NODES) { ok64 = 0; break; }
    }
    g_is64 = ok64;
}

// ---------------------- zero / init scratch ---------------------------------
__global__ void clear_kernel() {
    int stride = gridDim.x * blockDim.x;
    int gid = blockIdx.x * blockDim.x + threadIdx.x;
    for (int i = gid; i < N_NODES * C1; i += stride) g_out1[i] = 0.f;
    for (int i = gid; i < N_NODES * C2; i += stride) g_out2[i] = 0.f;
    for (int i = gid; i < N_NODES * H1; i += stride) { g_esum1[i] = 0.f; g_emax1[i] = 0u; }
    for (int i = gid; i < N_NODES;      i += stride) { g_esum2[i] = 0.f; g_emax2[i] = 0u; }
    for (int i = gid; i < G_GRAPHS * C2; i += stride) g_pool[i] = 0.f;
    for (int i = gid; i < G_GRAPHS;      i += stride) g_cnt[i] = 0;
}

// ---------------------- GEMM: C[M,N] = A[M,K] @ B[K,N] ----------------------
// 64x64 tile, TK=32, 256 threads, 4x4 micro-tile per thread. N,K multiples of
// 32/64 here (N in {256,64}, K in {128,256}); only M needs guarding.
__global__ void gemm_kernel(const float* __restrict__ A, const float* __restrict__ B,
                            float* __restrict__ C, int M, int N, int K) {
    __shared__ float As[64][33];
    __shared__ float Bs[32][68];
    int tid = threadIdx.x;
    int tx = tid & 15, ty = tid >> 4;
    int row0 = blockIdx.y * 64, col0 = blockIdx.x * 64;
    float acc[4][4];
#pragma unroll
    for (int i = 0; i < 4; i++)
#pragma unroll
        for (int j = 0; j < 4; j++) acc[i][j] = 0.f;

    for (int k0 = 0; k0 < K; k0 += 32) {
#pragma unroll
        for (int i = 0; i < 8; i++) {
            int r = (tid >> 5) + i * 8;
            int rr = row0 + r;
            As[r][tid & 31] = (rr < M) ? A[(size_t)rr * K + k0 + (tid & 31)] : 0.f;
        }
#pragma unroll
        for (int i = 0; i < 8; i++) {
            int kk = (tid >> 6) + i * 4;
            Bs[kk][tid & 63] = B[(size_t)(k0 + kk) * N + col0 + (tid & 63)];
        }
        __syncthreads();
#pragma unroll
        for (int k = 0; k < 32; k++) {
            float a0 = As[ty * 4 + 0][k];
            float a1 = As[ty * 4 + 1][k];
            float a2 = As[ty * 4 + 2][k];
            float a3 = As[ty * 4 + 3][k];
            float4 b = *(const float4*)&Bs[k][tx * 4];
            acc[0][0] += a0 * b.x; acc[0][1] += a0 * b.y; acc[0][2] += a0 * b.z; acc[0][3] += a0 * b.w;
            acc[1][0] += a1 * b.x; acc[1][1] += a1 * b.y; acc[1][2] += a1 * b.z; acc[1][3] += a1 * b.w;
            acc[2][0] += a2 * b.x; acc[2][1] += a2 * b.y; acc[2][2] += a2 * b.z; acc[2][3] += a2 * b.w;
            acc[3][0] += a3 * b.x; acc[3][1] += a3 * b.y; acc[3][2] += a3 * b.z; acc[3][3] += a3 * b.w;
        }
        __syncthreads();
    }
#pragma unroll
    for (int i = 0; i < 4; i++) {
        int row = row0 + ty * 4 + i;
        if (row < M) {
            float4 v = make_float4(acc[i][0], acc[i][1], acc[i][2], acc[i][3]);
            *(float4*)&C[(size_t)row * N + col0 + tx * 4] = v;
        }
    }
}

// ---------------------- per-node attention logits ----------------------------
// one warp per node; H heads of 64 channels each
template <int H>
__global__ void alpha_kernel(const float* __restrict__ h,
                             const float* __restrict__ att_src,
                             const float* __restrict__ att_dst,
                             float* __restrict__ asrc, float* __restrict__ adst) {
    int warp = (blockIdx.x * blockDim.x + threadIdx.x) >> 5;
    int lane = threadIdx.x & 31;
    if (warp >= N_NODES) return;
    const float* hrow = h + (size_t)warp * (H * 64);
#pragma unroll
    for (int hd = 0; hd < H; hd++) {
        float s = 0.f, d = 0.f;
#pragma unroll
        for (int c = lane; c < 64; c += 32) {
            float v = hrow[hd * 64 + c];
            s += v * __ldg(&att_src[hd * 64 + c]);
            d += v * __ldg(&att_dst[hd * 64 + c]);
        }
#pragma unroll
        for (int o = 16; o; o >>= 1) {
            s += __shfl_down_sync(0xFFFFFFFFu, s, o);
            d += __shfl_down_sync(0xFFFFFFFFu, d, o);
        }
        if (lane == 0) { asrc[warp * H + hd] = s; adst[warp * H + hd] = d; }
    }
}

// ---------------------- edge pass 1: segment max -----------------------------
template <int H>
__global__ void edge_max_kernel(const void* __restrict__ ei,
                                const float* __restrict__ asrc,
                                const float* __restrict__ adst,
                                unsigned* __restrict__ emax) {
    int e = blockIdx.x * blockDim.x + threadIdx.x;
    if (e >= E_TOT) return;
    int s, d;
    if (e < E_EDGES) { s = idx_at(ei, e); d = idx_at(ei, E_EDGES + e); }
    else { s = d = e - E_EDGES; }
#pragma unroll
    for (int h = 0; h < H; h++) {
        float v = asrc[s * H + h] + adst[d * H + h];
        v = v > 0.f ? v : NEG_SLOPE * v;
        atomicMax(&emax[d * H + h], enc_f(v));
    }
}

// ---------------------- edge pass 2: exp + segment sum -----------------------
template <int H>
__global__ void edge_sum_kernel(const void* __restrict__ ei,
                                const float* __restrict__ asrc,
                                const float* __restrict__ adst,
                                const unsigned* __restrict__ emax,
                                float* __restrict__ esum,
                                float* __restrict__ wbuf) {
    int e = blockIdx.x * blockDim.x + threadIdx.x;
    if (e >= E_TOT) return;
    int s, d;
    if (e < E_EDGES) { s = idx_at(ei, e); d = idx_at(ei, E_EDGES + e); }
    else { s = d = e - E_EDGES; }
#pragma unroll
    for (int h = 0; h < H; h++) {
        float v = asrc[s * H + h] + adst[d * H + h];
        v = v > 0.f ? v : NEG_SLOPE * v;
        float m = dec_f(emax[d * H + h]);
        float w = __expf(v - m);
        wbuf[e * H + h] = w;
        atomicAdd(&esum[d * H + h], w);
    }
}

// ---------------------- edge pass 3: weighted scatter ------------------------
// TPE = H*CH/4 threads per edge, each thread handles one float4 slice
template <int H, int CH>
__global__ void edge_scatter_kernel(const void* __restrict__ ei,
                                    const float* __restrict__ hfeat,
                                    const float* __restrict__ wbuf,
                                    const float* __restrict__ esum,
                                    float* __restrict__ out) {
    constexpr int TPE = (H * CH) / 4;
    int gt = blockIdx.x * blockDim.x + threadIdx.x;
    int e = gt / TPE;
    int t = gt - e * TPE;
    if (e >= E_TOT) return;
    int s, d;
    if (e < E_EDGES) { s = idx_at(ei, e); d = idx_at(ei, E_EDGES + e); }
    else { s = d = e - E_EDGES; }
    int h = (t * 4) / CH;
    float a = wbuf[e * H + h] / (esum[d * H + h] + 1e-16f);
    float4 v = *(const float4*)(hfeat + (size_t)s * (H * CH) + t * 4);
    float* o = out + (size_t)d * (H * CH) + t * 4;
    atomicAdd(o + 0, v.x * a);
    atomicAdd(o + 1, v.y * a);
    atomicAdd(o + 2, v.z * a);
    atomicAdd(o + 3, v.w * a);
}

// ---------------------- bias + ELU (in place) --------------------------------
__global__ void bias_elu_kernel(float* __restrict__ x, const float* __restrict__ b,
                                int n, int C) {
    int i = blockIdx.x * blockDim.x + threadIdx.x;
    if (i >= n) return;
    int c = i % C;
    float v = x[i] + __ldg(&b[c]);
    x[i] = v > 0.f ? v : expm1f(v);
}

// ---------------------- graph mean-pool accumulation -------------------------
__global__ void pool_kernel(const void* __restrict__ batch,
                            const float* __restrict__ feat) {
    int i = blockIdx.x * blockDim.x + threadIdx.x;
    if (i >= N_NODES * C2) return;
    int n = i / C2;
    int c = i - n * C2;
    int g = idx_at(batch, n);
    atomicAdd(&g_pool[g * C2 + c], feat[i]);
    if (c == 0) atomicAdd(&g_cnt[g], 1);
}

// ---------------------- final MLP (tiny) --------------------------------------
__global__ void mlp_kernel(const float* __restrict__ w1, const float* __restrict__ bb1,
                           const float* __restrict__ w2, const float* __restrict__ bb2,
                           float* __restrict__ outp) {
    __shared__ float ps[G_GRAPHS * C2];
    __shared__ float zs[G_GRAPHS * 128];
    for (int i = threadIdx.x; i < G_GRAPHS * C2; i += blockDim.x) {
        int g = i / C2;
        float c = (float)g_cnt[g];
        ps[i] = g_pool[i] / fmaxf(c, 1.f);
    }
    __syncthreads();
    int j = threadIdx.x;  // 0..127
    for (int g = 0; g < G_GRAPHS; g++) {
        float acc = bb1[j];
#pragma unroll 8
        for (int c = 0; c < C2; c++) acc += ps[g * C2 + c] * w1[c * 128 + j];
        zs[g * 128 + j] = fmaxf(acc, 0.f);
    }
    __syncthreads();
    if (threadIdx.x < G_GRAPHS) {
        int g = threadIdx.x;
        float acc = bb2[0];
#pragma unroll 8
        for (int k = 0; k < 128; k++) acc += zs[g * 128 + k] * w2[k];
        outp[g] = acc;
    }
}

// =============================================================================
extern "C" void kernel_launch(void* const* d_in, const int* in_sizes, int n_in,
                              void* d_out, int out_size) {
    // Map inputs by element count (robust to metadata ordering; within each
    // ambiguous size group the relative order att_src < att_dst < b and
    // lin1_b < lin2_w holds in both candidate orderings).
    const float *x = nullptr, *W1 = nullptr, *as1 = nullptr, *ad1 = nullptr, *b1 = nullptr;
    const float *W2 = nullptr, *as2 = nullptr, *ad2 = nullptr, *b2 = nullptr;
    const float *l1w = nullptr, *l1b = nullptr, *l2w = nullptr, *l2b = nullptr;
    const void *ei = nullptr, *batch = nullptr;
    int n256 = 0, n64 = 0, n128 = 0;
    for (int i = 0; i < n_in; i++) {
        const void* p = d_in[i];
        switch (in_sizes[i]) {
            case 6400000: x = (const float*)p; break;
            case 1600000: ei = p; break;
            case 50000:   batch = p; break;
            case 32768:   W1 = (const float*)p; break;
            case 16384:   W2 = (const float*)p; break;
            case 8192:    l1w = (const float*)p; break;
            case 1:       l2b = (const float*)p; break;
            case 256:
                if (n256 == 0) as1 = (const float*)p;
                else if (n256 == 1) ad1 = (const float*)p;
                else b1 = (const float*)p;
                n256++;
                break;
            case 64:
                if (n64 == 0) as2 = (const float*)p;
                else if (n64 == 1) ad2 = (const float*)p;
                else b2 = (const float*)p;
                n64++;
                break;
            case 128:
                if (n128 == 0) l1b = (const float*)p;
                else l2w = (const float*)p;
                n128++;
                break;
            default: break;
        }
    }
    float* outp = (float*)d_out;

    float* h1;    cudaGetSymbolAddress((void**)&h1, g_h1);
    float* out1;  cudaGetSymbolAddress((void**)&out1, g_out1);
    float* h2;    cudaGetSymbolAddress((void**)&h2, g_h2);
    float* out2;  cudaGetSymbolAddress((void**)&out2, g_out2);
    float* asr1;  cudaGetSymbolAddress((void**)&asr1, g_asrc1);
    float* ads1;  cudaGetSymbolAddress((void**)&ads1, g_adst1);
    unsigned* em1; cudaGetSymbolAddress((void**)&em1, g_emax1);
    float* es1;   cudaGetSymbolAddress((void**)&es1, g_esum1);
    float* asr2;  cudaGetSymbolAddress((void**)&asr2, g_asrc2);
    float* ads2;  cudaGetSymbolAddress((void**)&ads2, g_adst2);
    unsigned* em2; cudaGetSymbolAddress((void**)&em2, g_emax2);
    float* es2;   cudaGetSymbolAddress((void**)&es2, g_esum2);
    float* w1e;   cudaGetSymbolAddress((void**)&w1e, g_w1e);
    float* w2e;   cudaGetSymbolAddress((void**)&w2e, g_w2e);

    const int BT = 256;

    // -1. detect index dtype (int64 vs int32) once; subsequent kernels branch on it
    detect_kernel<<<1, 1>>>(ei);

    // 0. clear all accumulators
    clear_kernel<<<2048, BT>>>();

    // 1. h1 = x @ W1  (50000x128 @ 128x256)
    {
        dim3 grid(C1 / 64, (N_NODES + 63) / 64);
        gemm_kernel<<<grid, 256>>>(x, W1, h1, N_NODES, C1, 128);
    }
    // 2. attention logits layer 1
    {
        int blocks = (N_NODES * 32 + BT - 1) / BT;
        alpha_kernel<H1><<<blocks, BT>>>(h1, as1, ad1, asr1, ads1);
    }
    // 3-5. edge softmax + scatter layer 1
    {
        int eb = (E_TOT + BT - 1) / BT;
        edge_max_kernel<H1><<<eb, BT>>>(ei, asr1, ads1, em1);
        edge_sum_kernel<H1><<<eb, BT>>>(ei, asr1, ads1, em1, es1, w1e);
        long long tot = (long long)E_TOT * (H1 * 64 / 4);
        int sb = (int)((tot + BT - 1) / BT);
        edge_scatter_kernel<H1, 64><<<sb, BT>>>(ei, h1, w1e, es1, out1);
    }
    // 6. bias + elu layer 1 (in place)
    {
        int n = N_NODES * C1;
        bias_elu_kernel<<<(n + BT - 1) / BT, BT>>>(out1, b1, n, C1);
    }
    // 7. h2 = out1 @ W2  (50000x256 @ 256x64)
    {
        dim3 grid(C2 / 64, (N_NODES + 63) / 64);
        gemm_kernel<<<grid, 256>>>(out1, W2, h2, N_NODES, C2, 256);
    }
    // 8. attention logits layer 2
    {
        int blocks = (N_NODES * 32 + BT - 1) / BT;
        alpha_kernel<1><<<blocks, BT>>>(h2, as2, ad2, asr2, ads2);
    }
    // 9-11. edge softmax + scatter layer 2
    {
        int eb = (E_TOT + BT - 1) / BT;
        edge_max_kernel<1><<<eb, BT>>>(ei, asr2, ads2, em2);
        edge_sum_kernel<1><<<eb, BT>>>(ei, asr2, ads2, em2, es2, w2e);
        long long tot = (long long)E_TOT * (1 * 64 / 4);
        int sb = (int)((tot + BT - 1) / BT);
        edge_scatter_kernel<1, 64><<<sb, BT>>>(ei, h2, w2e, es2, out2);
    }
    // 12. bias + elu layer 2
    {
        int n = N_NODES * C2;
        bias_elu_kernel<<<(n + BT - 1) / BT, BT>>>(out2, b2, n, C2);
    }
    // 13. mean pool
    {
        int n = N_NODES * C2;
        pool_kernel<<<(n + BT - 1) / BT, BT>>>(batch, out2);
    }
    // 14. MLP head
    mlp_kernel<<<1, 128>>>(l1w, l1b, l2w, l2b, outp);
}

// round 3
// speedup vs baseline: 2.1522x; 2.1522x over previous
#include <cuda_runtime.h>
#include <cstdint>

// Problem constants (fixed by reference)
#define N_NODES 50000
#define E_EDGES 800000
#define G_GRAPHS 64
#define C1 256           // HEADS*HID after layer 1
#define C2 64            // HID after layer 2
#define H1 4             // heads layer 1
#define NEG_SLOPE 0.2f

// ------------------------- device scratch (no allocs allowed) ---------------
__device__ float g_h1[N_NODES * C1];        // x @ W1
__device__ float g_out1[N_NODES * C1];      // layer1 output (agg + bias + elu)
__device__ float g_h2[N_NODES * C2];        // out1 @ W2
__device__ float g_out2[N_NODES * C2];      // layer2 output
__device__ float g_asrc1[N_NODES * H1];
__device__ float g_adst1[N_NODES * H1];
__device__ float g_asrc2[N_NODES];
__device__ float g_adst2[N_NODES];
__device__ float g_pool[G_GRAPHS * C2];
__device__ int   g_cnt[G_GRAPHS];
__device__ int   g_is64;                    // 1 if indices are int64, 0 if int32
// CSR by destination (rebuilt every launch; cheap)
__device__ int g_deg[N_NODES];
__device__ int g_fill[N_NODES];
__device__ int g_rowptr[N_NODES + 1];
__device__ int g_esrc[E_EDGES];

// ---------------------- helpers ---------------------------------------------
__device__ __forceinline__ int idx_at(const void* __restrict__ p, int i) {
    if (g_is64) return (int)((const long long*)p)[i];
    return ((const int*)p)[i];
}

// ---------------------- dtype detection -------------------------------------
__global__ void detect_kernel(const void* __restrict__ ei) {
    const long long* p = (const long long*)ei;
    int ok64 = 1;
    for (int i = 0; i < 64; i++) {
        long long v = p[i];
        if (v < 0 || v >= N_NODES) { ok64 = 0; break; }
    }
    g_is64 = ok64;
}

// ---------------------- zero scratch -----------------------------------------
__global__ void clear_kernel() {
    int stride = gridDim.x * blockDim.x;
    int gid = blockIdx.x * blockDim.x + threadIdx.x;
    for (int i = gid; i < N_NODES; i += stride) { g_deg[i] = 0; g_fill[i] = 0; }
    for (int i = gid; i < G_GRAPHS * C2; i += stride) g_pool[i] = 0.f;
    for (int i = gid; i < G_GRAPHS; i += stride) g_cnt[i] = 0;
}

// ---------------------- CSR build --------------------------------------------
__global__ void count_kernel(const void* __restrict__ ei) {
    int e = blockIdx.x * blockDim.x + threadIdx.x;
    if (e >= E_EDGES) return;
    int d = idx_at(ei, E_EDGES + e);
    atomicAdd(&g_deg[d], 1);
}

// single-block exclusive scan of g_deg -> g_rowptr (1024 threads)
__global__ void scan_kernel() {
    __shared__ int sums[1024];
    int t = threadIdx.x;
    const int CHK = (N_NODES + 1023) / 1024;  // 49
    int start = t * CHK;
    int end = start + CHK; if (end > N_NODES) end = N_NODES;
    if (start > N_NODES) start = N_NODES;
    int s = 0;
    for (int i = start; i < end; i++) s += g_deg[i];
    sums[t] = s;
    __syncthreads();
    for (int off = 1; off < 1024; off <<= 1) {
        int v = 0;
        if (t >= off) v = sums[t - off];
        __syncthreads();
        if (t >= off) sums[t] += v;
        __syncthreads();
    }
    int base = (t == 0) ? 0 : sums[t - 1];
    for (int i = start; i < end; i++) { g_rowptr[i] = base; base += g_deg[i]; }
    if (t == 1023) g_rowptr[N_NODES] = sums[1023];
}

__global__ void fill_kernel(const void* __restrict__ ei) {
    int e = blockIdx.x * blockDim.x + threadIdx.x;
    if (e >= E_EDGES) return;
    int s = idx_at(ei, e);
    int d = idx_at(ei, E_EDGES + e);
    int slot = g_rowptr[d] + atomicAdd(&g_fill[d], 1);
    g_esrc[slot] = s;
}

// ---------------------- GEMM: C[M,N] = A[M,K] @ B[K,N] ----------------------
__global__ void gemm_kernel(const float* __restrict__ A, const float* __restrict__ B,
                            float* __restrict__ C, int M, int N, int K) {
    __shared__ float As[64][33];
    __shared__ float Bs[32][68];
    int tid = threadIdx.x;
    int tx = tid & 15, ty = tid >> 4;
    int row0 = blockIdx.y * 64, col0 = blockIdx.x * 64;
    float acc[4][4];
#pragma unroll
    for (int i = 0; i < 4; i++)
#pragma unroll
        for (int j = 0; j < 4; j++) acc[i][j] = 0.f;

    for (int k0 = 0; k0 < K; k0 += 32) {
#pragma unroll
        for (int i = 0; i < 8; i++) {
            int r = (tid >> 5) + i * 8;
            int rr = row0 + r;
            As[r][tid & 31] = (rr < M) ? A[(size_t)rr * K + k0 + (tid & 31)] : 0.f;
        }
#pragma unroll
        for (int i = 0; i < 8; i++) {
            int kk = (tid >> 6) + i * 4;
            Bs[kk][tid & 63] = B[(size_t)(k0 + kk) * N + col0 + (tid & 63)];
        }
        __syncthreads();
#pragma unroll
        for (int k = 0; k < 32; k++) {
            float a0 = As[ty * 4 + 0][k];
            float a1 = As[ty * 4 + 1][k];
            float a2 = As[ty * 4 + 2][k];
            float a3 = As[ty * 4 + 3][k];
            float4 b = *(const float4*)&Bs[k][tx * 4];
            acc[0][0] += a0 * b.x; acc[0][1] += a0 * b.y; acc[0][2] += a0 * b.z; acc[0][3] += a0 * b.w;
            acc[1][0] += a1 * b.x; acc[1][1] += a1 * b.y; acc[1][2] += a1 * b.z; acc[1][3] += a1 * b.w;
            acc[2][0] += a2 * b.x; acc[2][1] += a2 * b.y; acc[2][2] += a2 * b.z; acc[2][3] += a2 * b.w;
            acc[3][0] += a3 * b.x; acc[3][1] += a3 * b.y; acc[3][2] += a3 * b.z; acc[3][3] += a3 * b.w;
        }
        __syncthreads();
    }
#pragma unroll
    for (int i = 0; i < 4; i++) {
        int row = row0 + ty * 4 + i;
        if (row < M) {
            float4 v = make_float4(acc[i][0], acc[i][1], acc[i][2], acc[i][3]);
            *(float4*)&C[(size_t)row * N + col0 + tx * 4] = v;
        }
    }
}

// ---------------------- per-node attention logits ----------------------------
template <int H>
__global__ void alpha_kernel(const float* __restrict__ h,
                             const float* __restrict__ att_src,
                             const float* __restrict__ att_dst,
                             float* __restrict__ asrc, float* __restrict__ adst) {
    int warp = (blockIdx.x * blockDim.x + threadIdx.x) >> 5;
    int lane = threadIdx.x & 31;
    if (warp >= N_NODES) return;
    const float* hrow = h + (size_t)warp * (H * 64);
#pragma unroll
    for (int hd = 0; hd < H; hd++) {
        float s = 0.f, d = 0.f;
#pragma unroll
        for (int c = lane; c < 64; c += 32) {
            float v = hrow[hd * 64 + c];
            s += v * __ldg(&att_src[hd * 64 + c]);
            d += v * __ldg(&att_dst[hd * 64 + c]);
        }
#pragma unroll
        for (int o = 16; o; o >>= 1) {
            s += __shfl_down_sync(0xFFFFFFFFu, s, o);
            d += __shfl_down_sync(0xFFFFFFFFu, d, o);
        }
        if (lane == 0) { asrc[warp * H + hd] = s; adst[warp * H + hd] = d; }
    }
}

// ---------------------- fused GAT aggregation (gather-side, no atomics) ------
// One warp per dst node. PER = H*CH/32 output floats per lane.
// Lane's head = (lane*PER)/CH. Includes self loop. Fuses softmax + weighted
// aggregation + bias + ELU.
template <int H, int CH>
__global__ void gat_agg_kernel(const float* __restrict__ h,
                               const float* __restrict__ asrc,
                               const float* __restrict__ adst,
                               const float* __restrict__ bias,
                               float* __restrict__ out) {
    constexpr int PER = (H * CH) / 32;
    int node = (blockIdx.x * blockDim.x + threadIdx.x) >> 5;
    int lane = threadIdx.x & 31;
    if (node >= N_NODES) return;
    int r0 = g_rowptr[node], r1 = g_rowptr[node + 1];
    const int head = (lane * PER) / CH;

    float ad[H];
#pragma unroll
    for (int hh = 0; hh < H; hh++) ad[hh] = __ldg(&adst[node * H + hh]);

    // ---- pass 1: per-head max over {self} ∪ neighbors ----
    float mx[H];
#pragma unroll
    for (int hh = 0; hh < H; hh++) {
        float v = __ldg(&asrc[node * H + hh]) + ad[hh];
        mx[hh] = v > 0.f ? v : NEG_SLOPE * v;
    }
    for (int i = r0 + lane; i < r1; i += 32) {
        int s = g_esrc[i];
#pragma unroll
        for (int hh = 0; hh < H; hh++) {
            float v = __ldg(&asrc[s * H + hh]) + ad[hh];
            v = v > 0.f ? v : NEG_SLOPE * v;
            mx[hh] = fmaxf(mx[hh], v);
        }
    }
#pragma unroll
    for (int hh = 0; hh < H; hh++)
#pragma unroll
        for (int o = 16; o; o >>= 1)
            mx[hh] = fmaxf(mx[hh], __shfl_xor_sync(0xFFFFFFFFu, mx[hh], o));

    // ---- pass 2: exp weights + weighted accumulation in registers ----
    float acc[PER];
#pragma unroll
    for (int j = 0; j < PER; j++) acc[j] = 0.f;
    float wsum = 0.f;
    float mh = mx[head];
    float adh = ad[head];

    // self loop
    {
        float v = __ldg(&asrc[node * H + head]) + adh;
        v = v > 0.f ? v : NEG_SLOPE * v;
        float w = __expf(v - mh);
        wsum += w;
        const float* hp = h + (size_t)node * (H * CH) + lane * PER;
        if constexpr (PER == 8) {
            float4 a = *(const float4*)hp;
            float4 b = *(const float4*)(hp + 4);
            acc[0] += w * a.x; acc[1] += w * a.y; acc[2] += w * a.z; acc[3] += w * a.w;
            acc[4] += w * b.x; acc[5] += w * b.y; acc[6] += w * b.z; acc[7] += w * b.w;
        } else {
            float2 a = *(const float2*)hp;
            acc[0] += w * a.x; acc[1] += w * a.y;
        }
    }
    // neighbors (all lanes walk the full list; per-lane channels)
    for (int i = r0; i < r1; i++) {
        int s = g_esrc[i];
        float v = __ldg(&asrc[s * H + head]) + adh;
        v = v > 0.f ? v : NEG_SLOPE * v;
        float w = __expf(v - mh);
        wsum += w;
        const float* hp = h + (size_t)s * (H * CH) + lane * PER;
        if constexpr (PER == 8) {
            float4 a = *(const float4*)hp;
            float4 b = *(const float4*)(hp + 4);
            acc[0] += w * a.x; acc[1] += w * a.y; acc[2] += w * a.z; acc[3] += w * a.w;
            acc[4] += w * b.x; acc[5] += w * b.y; acc[6] += w * b.z; acc[7] += w * b.w;
        } else {
            float2 a = *(const float2*)hp;
            acc[0] += w * a.x; acc[1] += w * a.y;
        }
    }

    float inv = 1.f / (wsum + 1e-16f);
    float* op = out + (size_t)node * (H * CH) + lane * PER;
#pragma unroll
    for (int j = 0; j < PER; j++) {
        float v = acc[j] * inv + __ldg(&bias[lane * PER + j]);
        op[j] = v > 0.f ? v : expm1f(v);
    }
}

// ---------------------- graph mean-pool accumulation -------------------------
__global__ void pool_kernel(const void* __restrict__ batch,
                            const float* __restrict__ feat) {
    int i = blockIdx.x * blockDim.x + threadIdx.x;
    if (i >= N_NODES * C2) return;
    int n = i / C2;
    int c = i - n * C2;
    int g = idx_at(batch, n);
    atomicAdd(&g_pool[g * C2 + c], feat[i]);
    if (c == 0) atomicAdd(&g_cnt[g], 1);
}

// ---------------------- final MLP (tiny) --------------------------------------
__global__ void mlp_kernel(const float* __restrict__ w1, const float* __restrict__ bb1,
                           const float* __restrict__ w2, const float* __restrict__ bb2,
                           float* __restrict__ outp) {
    __shared__ float ps[G_GRAPHS * C2];
    __shared__ float zs[G_GRAPHS * 128];
    for (int i = threadIdx.x; i < G_GRAPHS * C2; i += blockDim.x) {
        int g = i / C2;
        float c = (float)g_cnt[g];
        ps[i] = g_pool[i] / fmaxf(c, 1.f);
    }
    __syncthreads();
    int j = threadIdx.x;  // 0..127
    for (int g = 0; g < G_GRAPHS; g++) {
        float acc = bb1[j];
#pragma unroll 8
        for (int c = 0; c < C2; c++) acc += ps[g * C2 + c] * w1[c * 128 + j];
        zs[g * 128 + j] = fmaxf(acc, 0.f);
    }
    __syncthreads();
    if (threadIdx.x < G_GRAPHS) {
        int g = threadIdx.x;
        float acc = bb2[0];
#pragma unroll 8
        for (int k = 0; k < 128; k++) acc += zs[g * 128 + k] * w2[k];
        outp[g] = acc;
    }
}

// =============================================================================
extern "C" void kernel_launch(void* const* d_in, const int* in_sizes, int n_in,
                              void* d_out, int out_size) {
    const float *x = nullptr, *W1 = nullptr, *as1 = nullptr, *ad1 = nullptr, *b1 = nullptr;
    const float *W2 = nullptr, *as2 = nullptr, *ad2 = nullptr, *b2 = nullptr;
    const float *l1w = nullptr, *l1b = nullptr, *l2w = nullptr, *l2b = nullptr;
    const void *ei = nullptr, *batch = nullptr;
    int n256 = 0, n64 = 0, n128 = 0;
    for (int i = 0; i < n_in; i++) {
        const void* p = d_in[i];
        switch (in_sizes[i]) {
            case 6400000: x = (const float*)p; break;
            case 1600000: ei = p; break;
            case 50000:   batch = p; break;
            case 32768:   W1 = (const float*)p; break;
            case 16384:   W2 = (const float*)p; break;
            case 8192:    l1w = (const float*)p; break;
            case 1:       l2b = (const float*)p; break;
            case 256:
                if (n256 == 0) as1 = (const float*)p;
                else if (n256 == 1) ad1 = (const float*)p;
                else b1 = (const float*)p;
                n256++;
                break;
            case 64:
                if (n64 == 0) as2 = (const float*)p;
                else if (n64 == 1) ad2 = (const float*)p;
                else b2 = (const float*)p;
                n64++;
                break;
            case 128:
                if (n128 == 0) l1b = (const float*)p;
                else l2w = (const float*)p;
                n128++;
                break;
            default: break;
        }
    }
    float* outp = (float*)d_out;

    float* h1;    cudaGetSymbolAddress((void**)&h1, g_h1);
    float* out1;  cudaGetSymbolAddress((void**)&out1, g_out1);
    float* h2;    cudaGetSymbolAddress((void**)&h2, g_h2);
    float* out2;  cudaGetSymbolAddress((void**)&out2, g_out2);
    float* asr1;  cudaGetSymbolAddress((void**)&asr1, g_asrc1);
    float* ads1;  cudaGetSymbolAddress((void**)&ads1, g_adst1);
    float* asr2;  cudaGetSymbolAddress((void**)&asr2, g_asrc2);
    float* ads2;  cudaGetSymbolAddress((void**)&ads2, g_adst2);

    const int BT = 256;

    // index dtype detection + scratch clear
    detect_kernel<<<1, 1>>>(ei);
    clear_kernel<<<512, BT>>>();

    // CSR by destination
    {
        int eb = (E_EDGES + BT - 1) / BT;
        count_kernel<<<eb, BT>>>(ei);
        scan_kernel<<<1, 1024>>>();
        fill_kernel<<<eb, BT>>>(ei);
    }

    // layer 1
    {
        dim3 grid(C1 / 64, (N_NODES + 63) / 64);
        gemm_kernel<<<grid, 256>>>(x, W1, h1, N_NODES, C1, 128);
        int blocks = (N_NODES * 32 + BT - 1) / BT;
        alpha_kernel<H1><<<blocks, BT>>>(h1, as1, ad1, asr1, ads1);
        gat_agg_kernel<H1, 64><<<blocks, BT>>>(h1, asr1, ads1, b1, out1);
    }

    // layer 2
    {
        dim3 grid(C2 / 64, (N_NODES + 63) / 64);
        gemm_kernel<<<grid, 256>>>(out1, W2, h2, N_NODES, C2, 256);
        int blocks = (N_NODES * 32 + BT - 1) / BT;
        alpha_kernel<1><<<blocks, BT>>>(h2, as2, ad2, asr2, ads2);
        gat_agg_kernel<1, 64><<<blocks, BT>>>(h2, asr2, ads2, b2, out2);
    }

    // mean pool + MLP head
    {
        int n = N_NODES * C2;
        pool_kernel<<<(n + BT - 1) / BT, BT>>>(batch, out2);
        mlp_kernel<<<1, 128>>>(l1w, l1b, l2w, l2b, outp);
    }
}

// round 4
// speedup vs baseline: 2.2612x; 1.0507x over previous
#include <cuda_runtime.h>
#include <cstdint>

// Problem constants (fixed by reference)
#define N_NODES 50000
#define E_EDGES 800000
#define G_GRAPHS 64
#define C1 256           // HEADS*HID after layer 1
#define C2 64            // HID after layer 2
#define H1 4             // heads layer 1
#define NEG_SLOPE 0.2f
#define NB_SCAN ((N_NODES + 255) / 256)   // 196 scan blocks

// ------------------------- device scratch (no allocs allowed) ---------------
__device__ float g_h1[N_NODES * C1];
__device__ float g_out1[N_NODES * C1];
__device__ float g_h2[N_NODES * C2];
__device__ float g_out2[N_NODES * C2];
__device__ float g_asrc1[N_NODES * H1];
__device__ float g_adst1[N_NODES * H1];
__device__ float g_asrc2[N_NODES];
__device__ float g_adst2[N_NODES];
__device__ float g_pool[G_GRAPHS * C2];
__device__ int   g_cnt[G_GRAPHS];
__device__ int   g_is64;
// CSR by destination
__device__ int g_deg[N_NODES];
__device__ int g_fill[N_NODES];
__device__ int g_rowptr[N_NODES + 1];
__device__ int g_esrc[E_EDGES];
__device__ int g_bsum[NB_SCAN];

// ---------------------- helpers ---------------------------------------------
__device__ __forceinline__ int idx_at(const void* __restrict__ p, int i) {
    if (g_is64) return (int)((const long long*)p)[i];
    return ((const int*)p)[i];
}
__device__ __forceinline__ unsigned long long pack2(float lo, float hi) {
    unsigned long long r;
    asm("mov.b64 %0, {%1, %2};" : "=l"(r) : "f"(lo), "f"(hi));
    return r;
}
__device__ __forceinline__ void fma2(unsigned long long& d, unsigned long long a,
                                     unsigned long long b) {
    asm("fma.rn.f32x2 %0, %1, %2, %0;" : "+l"(d) : "l"(a), "l"(b));
}

// ---------------------- dtype detection -------------------------------------
__global__ void detect_kernel(const void* __restrict__ ei) {
    const long long* p = (const long long*)ei;
    int ok64 = 1;
    for (int i = 0; i < 64; i++) {
        long long v = p[i];
        if (v < 0 || v >= N_NODES) { ok64 = 0; break; }
    }
    g_is64 = ok64;
}

// ---------------------- zero scratch -----------------------------------------
__global__ void clear_kernel() {
    int stride = gridDim.x * blockDim.x;
    int gid = blockIdx.x * blockDim.x + threadIdx.x;
    for (int i = gid; i < N_NODES; i += stride) { g_deg[i] = 0; g_fill[i] = 0; }
    for (int i = gid; i < G_GRAPHS * C2; i += stride) g_pool[i] = 0.f;
    for (int i = gid; i < G_GRAPHS; i += stride) g_cnt[i] = 0;
}

// ---------------------- CSR build --------------------------------------------
__global__ void count_kernel(const void* __restrict__ ei) {
    int e = blockIdx.x * blockDim.x + threadIdx.x;
    if (e >= E_EDGES) return;
    int d = idx_at(ei, E_EDGES + e);
    atomicAdd(&g_deg[d], 1);
}

// hierarchical exclusive scan of g_deg -> g_rowptr
__global__ void scan1_kernel() {       // grid NB_SCAN, block 256: block sums
    __shared__ int sh[256];
    int i = blockIdx.x * 256 + threadIdx.x;
    sh[threadIdx.x] = (i < N_NODES) ? g_deg[i] : 0;
    __syncthreads();
    for (int off = 128; off; off >>= 1) {
        if (threadIdx.x < off) sh[threadIdx.x] += sh[threadIdx.x + off];
        __syncthreads();
    }
    if (threadIdx.x == 0) g_bsum[blockIdx.x] = sh[0];
}
__global__ void scan2_kernel() {       // 1 block, 256 threads: inclusive scan of block sums
    __shared__ int sh[256];
    int t = threadIdx.x;
    sh[t] = (t < NB_SCAN) ? g_bsum[t] : 0;
    __syncthreads();
    for (int off = 1; off < 256; off <<= 1) {
        int v = (t >= off) ? sh[t - off] : 0;
        __syncthreads();
        sh[t] += v;
        __syncthreads();
    }
    if (t < NB_SCAN) g_bsum[t] = sh[t];
}
__global__ void scan3_kernel() {       // per-block exclusive scan + base
    __shared__ int sh[256];
    int t = threadIdx.x;
    int i = blockIdx.x * 256 + t;
    int v = (i < N_NODES) ? g_deg[i] : 0;
    sh[t] = v;
    __syncthreads();
    for (int off = 1; off < 256; off <<= 1) {
        int u = (t >= off) ? sh[t - off] : 0;
        __syncthreads();
        sh[t] += u;
        __syncthreads();
    }
    int base = blockIdx.x ? g_bsum[blockIdx.x - 1] : 0;
    if (i < N_NODES) g_rowptr[i] = base + sh[t] - v;        // exclusive
    if (i == N_NODES - 1) g_rowptr[N_NODES] = base + sh[t]; // total
}

__global__ void fill_kernel(const void* __restrict__ ei) {
    int e = blockIdx.x * blockDim.x + threadIdx.x;
    if (e >= E_EDGES) return;
    int s = idx_at(ei, e);
    int d = idx_at(ei, E_EDGES + e);
    int slot = g_rowptr[d] + atomicAdd(&g_fill[d], 1);
    g_esrc[slot] = s;
}

// ---------------------- GEMM: C[M,N] = A[M,K] @ B[K,N] ----------------------
// BM=128, BK=16, TM=TN=8, packed f32x2 accumulation (2 MAC per FFMA2).
// threads = 16 * (BN/8); BN=128 -> 256 thr, BN=64 -> 128 thr. K % 16 == 0.
template <int BN>
__global__ void gemm_kernel(const float* __restrict__ A, const float* __restrict__ B,
                            float* __restrict__ C, int M, int N, int K) {
    constexpr int BM = 128, BK = 16;
    constexpr int NT = 16 * (BN / 8);
    __shared__ float As[BK][BM + 4];   // transposed; stride 132 (16B-aligned rows)
    __shared__ float Bs[BK][BN];

    int tid = threadIdx.x;
    int tx = tid % (BN / 8);
    int ty = tid / (BN / 8);
    int row0 = blockIdx.y * BM, col0 = blockIdx.x * BN;

    unsigned long long acc[8][4];
#pragma unroll
    for (int m = 0; m < 8; m++)
#pragma unroll
        for (int nn = 0; nn < 4; nn++) acc[m][nn] = 0ULL;

    for (int k0 = 0; k0 < K; k0 += BK) {
        // load A tile (BM x BK), store transposed
        constexpr int A4 = BM * BK / 4;
#pragma unroll
        for (int f = tid; f < A4; f += NT) {
            int r = f / (BK / 4);
            int c4 = f % (BK / 4);
            int rr = row0 + r;
            float4 v = make_float4(0.f, 0.f, 0.f, 0.f);
            if (rr < M) v = *(const float4*)&A[(size_t)rr * K + k0 + c4 * 4];
            As[c4 * 4 + 0][r] = v.x;
            As[c4 * 4 + 1][r] = v.y;
            As[c4 * 4 + 2][r] = v.z;
            As[c4 * 4 + 3][r] = v.w;
        }
        // load B tile (BK x BN)
        constexpr int B4 = BK * BN / 4;
#pragma unroll
        for (int f = tid; f < B4; f += NT) {
            int r = f / (BN / 4);
            int c4 = f % (BN / 4);
            *(float4*)&Bs[r][c4 * 4] = *(const float4*)&B[(size_t)(k0 + r) * N + col0 + c4 * 4];
        }
        __syncthreads();
#pragma unroll
        for (int k = 0; k < BK; k++) {
            float4 a0 = *(const float4*)&As[k][ty * 8];
            float4 a1 = *(const float4*)&As[k][ty * 8 + 4];
            const unsigned long long* bp = (const unsigned long long*)&Bs[k][tx * 8];
            unsigned long long b0 = bp[0], b1 = bp[1], b2 = bp[2], b3 = bp[3];
            float am[8] = {a0.x, a0.y, a0.z, a0.w, a1.x, a1.y, a1.z, a1.w};
#pragma unroll
            for (int m = 0; m < 8; m++) {
                unsigned long long ap = pack2(am[m], am[m]);
                fma2(acc[m][0], ap, b0);
                fma2(acc[m][1], ap, b1);
                fma2(acc[m][2], ap, b2);
                fma2(acc[m][3], ap, b3);
            }
        }
        __syncthreads();
    }
#pragma unroll
    for (int m = 0; m < 8; m++) {
        int row = row0 + ty * 8 + m;
        if (row < M) {
            unsigned long long* cp = (unsigned long long*)&C[(size_t)row * N + col0 + tx * 8];
            cp[0] = acc[m][0];
            cp[1] = acc[m][1];
            cp[2] = acc[m][2];
            cp[3] = acc[m][3];
        }
    }
}

// ---------------------- per-node attention logits ----------------------------
template <int H>
__global__ void alpha_kernel(const float* __restrict__ h,
                             const float* __restrict__ att_src,
                             const float* __restrict__ att_dst,
                             float* __restrict__ asrc, float* __restrict__ adst) {
    int warp = (blockIdx.x * blockDim.x + threadIdx.x) >> 5;
    int lane = threadIdx.x & 31;
    if (warp >= N_NODES) return;
    const float* hrow = h + (size_t)warp * (H * 64);
#pragma unroll
    for (int hd = 0; hd < H; hd++) {
        float s = 0.f, d = 0.f;
#pragma unroll
        for (int c = lane; c < 64; c += 32) {
            float v = hrow[hd * 64 + c];
            s += v * __ldg(&att_src[hd * 64 + c]);
            d += v * __ldg(&att_dst[hd * 64 + c]);
        }
#pragma unroll
        for (int o = 16; o; o >>= 1) {
            s += __shfl_down_sync(0xFFFFFFFFu, s, o);
            d += __shfl_down_sync(0xFFFFFFFFu, d, o);
        }
        if (lane == 0) { asrc[warp * H + hd] = s; adst[warp * H + hd] = d; }
    }
}

// ---------------------- fused GAT aggregation (gather-side, no atomics) ------
template <int H, int CH>
__global__ void gat_agg_kernel(const float* __restrict__ h,
                               const float* __restrict__ asrc,
                               const float* __restrict__ adst,
                               const float* __restrict__ bias,
                               float* __restrict__ out) {
    constexpr int PER = (H * CH) / 32;
    int node = (blockIdx.x * blockDim.x + threadIdx.x) >> 5;
    int lane = threadIdx.x & 31;
    if (node >= N_NODES) return;
    int r0 = g_rowptr[node], r1 = g_rowptr[node + 1];
    const int head = (lane * PER) / CH;

    float ad[H];
#pragma unroll
    for (int hh = 0; hh < H; hh++) ad[hh] = __ldg(&adst[node * H + hh]);

    float mx[H];
#pragma unroll
    for (int hh = 0; hh < H; hh++) {
        float v = __ldg(&asrc[node * H + hh]) + ad[hh];
        mx[hh] = v > 0.f ? v : NEG_SLOPE * v;
    }
    for (int i = r0 + lane; i < r1; i += 32) {
        int s = g_esrc[i];
#pragma unroll
        for (int hh = 0; hh < H; hh++) {
            float v = __ldg(&asrc[s * H + hh]) + ad[hh];
            v = v > 0.f ? v : NEG_SLOPE * v;
            mx[hh] = fmaxf(mx[hh], v);
        }
    }
#pragma unroll
    for (int hh = 0; hh < H; hh++)
#pragma unroll
        for (int o = 16; o; o >>= 1)
            mx[hh] = fmaxf(mx[hh], __shfl_xor_sync(0xFFFFFFFFu, mx[hh], o));

    float acc[PER];
#pragma unroll
    for (int j = 0; j < PER; j++) acc[j] = 0.f;
    float wsum = 0.f;
    float mh = mx[head];
    float adh = ad[head];

    {   // self loop
        float v = __ldg(&asrc[node * H + head]) + adh;
        v = v > 0.f ? v : NEG_SLOPE * v;
        float w = __expf(v - mh);
        wsum += w;
        const float* hp = h + (size_t)node * (H * CH) + lane * PER;
        if constexpr (PER == 8) {
            float4 a = *(const float4*)hp;
            float4 b = *(const float4*)(hp + 4);
            acc[0] += w * a.x; acc[1] += w * a.y; acc[2] += w * a.z; acc[3] += w * a.w;
            acc[4] += w * b.x; acc[5] += w * b.y; acc[6] += w * b.z; acc[7] += w * b.w;
        } else {
            float2 a = *(const float2*)hp;
            acc[0] += w * a.x; acc[1] += w * a.y;
        }
    }
    for (int i = r0; i < r1; i++) {
        int s = g_esrc[i];
        float v = __ldg(&asrc[s * H + head]) + adh;
        v = v > 0.f ? v : NEG_SLOPE * v;
        float w = __expf(v - mh);
        wsum += w;
        const float* hp = h + (size_t)s * (H * CH) + lane * PER;
        if constexpr (PER == 8) {
            float4 a = *(const float4*)hp;
            float4 b = *(const float4*)(hp + 4);
            acc[0] += w * a.x; acc[1] += w * a.y; acc[2] += w * a.z; acc[3] += w * a.w;
            acc[4] += w * b.x; acc[5] += w * b.y; acc[6] += w * b.z; acc[7] += w * b.w;
        } else {
            float2 a = *(const float2*)hp;
            acc[0] += w * a.x; acc[1] += w * a.y;
        }
    }

    float inv = 1.f / (wsum + 1e-16f);
    float* op = out + (size_t)node * (H * CH) + lane * PER;
#pragma unroll
    for (int j = 0; j < PER; j++) {
        float v = acc[j] * inv + __ldg(&bias[lane * PER + j]);
        op[j] = v > 0.f ? v : expm1f(v);
    }
}

// ---------------------- graph mean-pool accumulation -------------------------
__global__ void pool_kernel(const void* __restrict__ batch,
                            const float* __restrict__ feat) {
    int i = blockIdx.x * blockDim.x + threadIdx.x;
    if (i >= N_NODES * C2) return;
    int n = i / C2;
    int c = i - n * C2;
    int g = idx_at(batch, n);
    atomicAdd(&g_pool[g * C2 + c], feat[i]);
    if (c == 0) atomicAdd(&g_cnt[g], 1);
}

// ---------------------- final MLP (tiny) --------------------------------------
__global__ void mlp_kernel(const float* __restrict__ w1, const float* __restrict__ bb1,
                           const float* __restrict__ w2, const float* __restrict__ bb2,
                           float* __restrict__ outp) {
    __shared__ float ps[G_GRAPHS * C2];
    __shared__ float zs[G_GRAPHS * 128];
    for (int i = threadIdx.x; i < G_GRAPHS * C2; i += blockDim.x) {
        int g = i / C2;
        float c = (float)g_cnt[g];
        ps[i] = g_pool[i] / fmaxf(c, 1.f);
    }
    __syncthreads();
    int j = threadIdx.x;  // 0..127
    for (int g = 0; g < G_GRAPHS; g++) {
        float acc = bb1[j];
#pragma unroll 8
        for (int c = 0; c < C2; c++) acc += ps[g * C2 + c] * w1[c * 128 + j];
        zs[g * 128 + j] = fmaxf(acc, 0.f);
    }
    __syncthreads();
    if (threadIdx.x < G_GRAPHS) {
        int g = threadIdx.x;
        float acc = bb2[0];
#pragma unroll 8
        for (int k = 0; k < 128; k++) acc += zs[g * 128 + k] * w2[k];
        outp[g] = acc;
    }
}

// =============================================================================
extern "C" void kernel_launch(void* const* d_in, const int* in_sizes, int n_in,
                              void* d_out, int out_size) {
    const float *x = nullptr, *W1 = nullptr, *as1 = nullptr, *ad1 = nullptr, *b1 = nullptr;
    const float *W2 = nullptr, *as2 = nullptr, *ad2 = nullptr, *b2 = nullptr;
    const float *l1w = nullptr, *l1b = nullptr, *l2w = nullptr, *l2b = nullptr;
    const void *ei = nullptr, *batch = nullptr;
    int n256 = 0, n64 = 0, n128 = 0;
    for (int i = 0; i < n_in; i++) {
        const void* p = d_in[i];
        switch (in_sizes[i]) {
            case 6400000: x = (const float*)p; break;
            case 1600000: ei = p; break;
            case 50000:   batch = p; break;
            case 32768:   W1 = (const float*)p; break;
            case 16384:   W2 = (const float*)p; break;
            case 8192:    l1w = (const float*)p; break;
            case 1:       l2b = (const float*)p; break;
            case 256:
                if (n256 == 0) as1 = (const float*)p;
                else if (n256 == 1) ad1 = (const float*)p;
                else b1 = (const float*)p;
                n256++;
                break;
            case 64:
                if (n64 == 0) as2 = (const float*)p;
                else if (n64 == 1) ad2 = (const float*)p;
                else b2 = (const float*)p;
                n64++;
                break;
            case 128:
                if (n128 == 0) l1b = (const float*)p;
                else l2w = (const float*)p;
                n128++;
                break;
            default: break;
        }
    }
    float* outp = (float*)d_out;

    float* h1;    cudaGetSymbolAddress((void**)&h1, g_h1);
    float* out1;  cudaGetSymbolAddress((void**)&out1, g_out1);
    float* h2;    cudaGetSymbolAddress((void**)&h2, g_h2);
    float* out2;  cudaGetSymbolAddress((void**)&out2, g_out2);
    float* asr1;  cudaGetSymbolAddress((void**)&asr1, g_asrc1);
    float* ads1;  cudaGetSymbolAddress((void**)&ads1, g_adst1);
    float* asr2;  cudaGetSymbolAddress((void**)&asr2, g_asrc2);
    float* ads2;  cudaGetSymbolAddress((void**)&ads2, g_adst2);

    const int BT = 256;

    detect_kernel<<<1, 1>>>(ei);
    clear_kernel<<<512, BT>>>();

    // CSR by destination
    {
        int eb = (E_EDGES + BT - 1) / BT;
        count_kernel<<<eb, BT>>>(ei);
        scan1_kernel<<<NB_SCAN, 256>>>();
        scan2_kernel<<<1, 256>>>();
        scan3_kernel<<<NB_SCAN, 256>>>();
        fill_kernel<<<eb, BT>>>(ei);
    }

    // layer 1
    {
        dim3 grid(C1 / 128, (N_NODES + 127) / 128);
        gemm_kernel<128><<<grid, 256>>>(x, W1, h1, N_NODES, C1, 128);
        int blocks = (N_NODES * 32 + BT - 1) / BT;
        alpha_kernel<H1><<<blocks, BT>>>(h1, as1, ad1, asr1, ads1);
        gat_agg_kernel<H1, 64><<<blocks, BT>>>(h1, asr1, ads1, b1, out1);
    }

    // layer 2
    {
        dim3 grid(1, (N_NODES + 127) / 128);
        gemm_kernel<64><<<grid, 128>>>(out1, W2, h2, N_NODES, C2, 256);
        int blocks = (N_NODES * 32 + BT - 1) / BT;
        alpha_kernel<1><<<blocks, BT>>>(h2, as2, ad2, asr2, ads2);
        gat_agg_kernel<1, 64><<<blocks, BT>>>(h2, asr2, ads2, b2, out2);
    }

    // mean pool + MLP head
    {
        int n = N_NODES * C2;
        pool_kernel<<<(n + BT - 1) / BT, BT>>>(batch, out2);
        mlp_kernel<<<1, 128>>>(l1w, l1b, l2w, l2b, outp);
    }
}

// round 5
// speedup vs baseline: 2.4231x; 1.0716x over previous
#include <cuda_runtime.h>
#include <cstdint>

// Problem constants (fixed by reference)
#define N_NODES 50000
#define E_EDGES 800000
#define G_GRAPHS 64
#define C1 256           // HEADS*HID after layer 1
#define C2 64            // HID after layer 2
#define H1 4             // heads layer 1
#define NEG_SLOPE 0.2f
#define NB_SCAN ((N_NODES + 255) / 256)   // 196 scan blocks

// ------------------------- device scratch (no allocs allowed) ---------------
__device__ float g_h1[N_NODES * C1];
__device__ float g_out1[N_NODES * C1];
__device__ float g_h2[N_NODES * C2];
__device__ float g_out2[N_NODES * C2];
__device__ float g_asrc1[N_NODES * H1];
__device__ float g_adst1[N_NODES * H1];
__device__ float g_asrc2[N_NODES];
__device__ float g_adst2[N_NODES];
__device__ float g_pool[G_GRAPHS * C2];
__device__ int   g_cnt[G_GRAPHS];
__device__ int   g_is64;
// CSR by destination
__device__ int g_deg[N_NODES];
__device__ int g_fill[N_NODES];
__device__ int g_rowptr[N_NODES + 1];
__device__ int g_esrc[E_EDGES];
__device__ int g_bsum[NB_SCAN];

// ---------------------- helpers ---------------------------------------------
__device__ __forceinline__ int idx_at(const void* __restrict__ p, int i) {
    if (g_is64) return (int)((const long long*)p)[i];
    return ((const int*)p)[i];
}
__device__ __forceinline__ unsigned long long pack2(float lo, float hi) {
    unsigned long long r;
    asm("mov.b64 %0, {%1, %2};" : "=l"(r) : "f"(lo), "f"(hi));
    return r;
}
__device__ __forceinline__ void unpack2(unsigned long long v, float& lo, float& hi) {
    asm("mov.b64 {%0, %1}, %2;" : "=f"(lo), "=f"(hi) : "l"(v));
}
__device__ __forceinline__ void fma2(unsigned long long& d, unsigned long long a,
                                     unsigned long long b) {
    asm("fma.rn.f32x2 %0, %1, %2, %0;" : "+l"(d) : "l"(a), "l"(b));
}

// ---------------------- clear + dtype detection ------------------------------
__global__ void clear_kernel(const void* __restrict__ ei) {
    int stride = gridDim.x * blockDim.x;
    int gid = blockIdx.x * blockDim.x + threadIdx.x;
    if (gid == 0) {   // dtype detection: int32 pairs read as int64 escape [0,N)
        const long long* p = (const long long*)ei;
        int ok64 = 1;
        for (int i = 0; i < 64; i++) {
            long long v = p[i];
            if (v < 0 || v >= N_NODES) { ok64 = 0; break; }
        }
        g_is64 = ok64;
    }
    for (int i = gid; i < N_NODES; i += stride) { g_deg[i] = 0; g_fill[i] = 0; }
    for (int i = gid; i < N_NODES * H1; i += stride) { g_asrc1[i] = 0.f; g_adst1[i] = 0.f; }
    for (int i = gid; i < N_NODES; i += stride) { g_asrc2[i] = 0.f; g_adst2[i] = 0.f; }
    for (int i = gid; i < G_GRAPHS * C2; i += stride) g_pool[i] = 0.f;
    for (int i = gid; i < G_GRAPHS; i += stride) g_cnt[i] = 0;
}

// ---------------------- CSR build --------------------------------------------
__global__ void count_kernel(const void* __restrict__ ei) {
    int e = blockIdx.x * blockDim.x + threadIdx.x;
    if (e >= E_EDGES) return;
    int d = idx_at(ei, E_EDGES + e);
    atomicAdd(&g_deg[d], 1);
}

__global__ void scan1_kernel() {       // block sums
    __shared__ int sh[256];
    int i = blockIdx.x * 256 + threadIdx.x;
    sh[threadIdx.x] = (i < N_NODES) ? g_deg[i] : 0;
    __syncthreads();
    for (int off = 128; off; off >>= 1) {
        if (threadIdx.x < off) sh[threadIdx.x] += sh[threadIdx.x + off];
        __syncthreads();
    }
    if (threadIdx.x == 0) g_bsum[blockIdx.x] = sh[0];
}
__global__ void scan2_kernel() {       // inclusive scan of block sums
    __shared__ int sh[256];
    int t = threadIdx.x;
    sh[t] = (t < NB_SCAN) ? g_bsum[t] : 0;
    __syncthreads();
    for (int off = 1; off < 256; off <<= 1) {
        int v = (t >= off) ? sh[t - off] : 0;
        __syncthreads();
        sh[t] += v;
        __syncthreads();
    }
    if (t < NB_SCAN) g_bsum[t] = sh[t];
}
__global__ void scan3_kernel() {       // per-block exclusive scan + base
    __shared__ int sh[256];
    int t = threadIdx.x;
    int i = blockIdx.x * 256 + t;
    int v = (i < N_NODES) ? g_deg[i] : 0;
    sh[t] = v;
    __syncthreads();
    for (int off = 1; off < 256; off <<= 1) {
        int u = (t >= off) ? sh[t - off] : 0;
        __syncthreads();
        sh[t] += u;
        __syncthreads();
    }
    int base = blockIdx.x ? g_bsum[blockIdx.x - 1] : 0;
    if (i < N_NODES) g_rowptr[i] = base + sh[t] - v;
    if (i == N_NODES - 1) g_rowptr[N_NODES] = base + sh[t];
}

__global__ void fill_kernel(const void* __restrict__ ei) {
    int e = blockIdx.x * blockDim.x + threadIdx.x;
    if (e >= E_EDGES) return;
    int s = idx_at(ei, e);
    int d = idx_at(ei, E_EDGES + e);
    int slot = g_rowptr[d] + atomicAdd(&g_fill[d], 1);
    g_esrc[slot] = s;
}

// ---------------------- GEMM + fused alpha epilogue --------------------------
// BM=128, BK=16, 8x8 micro-tile, packed f32x2 accumulation.
// threads = 16*(BN/8). Epilogue computes per-row partial dots with att_src /
// att_dst over this thread's 8 columns, shfl-reduces over the 8 lanes covering
// one 64-ch head, and atomicAdds into asrc/adst (zeroed beforehand).
template <int BN, int H>
__global__ void gemm_kernel(const float* __restrict__ A, const float* __restrict__ B,
                            float* __restrict__ C, int M, int N, int K,
                            const float* __restrict__ att_src,
                            const float* __restrict__ att_dst,
                            float* __restrict__ asrc, float* __restrict__ adst) {
    constexpr int BM = 128, BK = 16;
    constexpr int NT = 16 * (BN / 8);
    __shared__ float As[BK][BM + 4];
    __shared__ float Bs[BK][BN];

    int tid = threadIdx.x;
    int tx = tid % (BN / 8);
    int ty = tid / (BN / 8);
    int row0 = blockIdx.y * BM, col0 = blockIdx.x * BN;

    unsigned long long acc[8][4];
#pragma unroll
    for (int m = 0; m < 8; m++)
#pragma unroll
        for (int nn = 0; nn < 4; nn++) acc[m][nn] = 0ULL;

    for (int k0 = 0; k0 < K; k0 += BK) {
        constexpr int A4 = BM * BK / 4;
#pragma unroll
        for (int f = tid; f < A4; f += NT) {
            int r = f / (BK / 4);
            int c4 = f % (BK / 4);
            int rr = row0 + r;
            float4 v = make_float4(0.f, 0.f, 0.f, 0.f);
            if (rr < M) v = *(const float4*)&A[(size_t)rr * K + k0 + c4 * 4];
            As[c4 * 4 + 0][r] = v.x;
            As[c4 * 4 + 1][r] = v.y;
            As[c4 * 4 + 2][r] = v.z;
            As[c4 * 4 + 3][r] = v.w;
        }
        constexpr int B4 = BK * BN / 4;
#pragma unroll
        for (int f = tid; f < B4; f += NT) {
            int r = f / (BN / 4);
            int c4 = f % (BN / 4);
            *(float4*)&Bs[r][c4 * 4] = *(const float4*)&B[(size_t)(k0 + r) * N + col0 + c4 * 4];
        }
        __syncthreads();
#pragma unroll
        for (int k = 0; k < BK; k++) {
            float4 a0 = *(const float4*)&As[k][ty * 8];
            float4 a1 = *(const float4*)&As[k][ty * 8 + 4];
            const unsigned long long* bp = (const unsigned long long*)&Bs[k][tx * 8];
            unsigned long long b0 = bp[0], b1 = bp[1], b2 = bp[2], b3 = bp[3];
            float am[8] = {a0.x, a0.y, a0.z, a0.w, a1.x, a1.y, a1.z, a1.w};
#pragma unroll
            for (int m = 0; m < 8; m++) {
                unsigned long long ap = pack2(am[m], am[m]);
                fma2(acc[m][0], ap, b0);
                fma2(acc[m][1], ap, b1);
                fma2(acc[m][2], ap, b2);
                fma2(acc[m][3], ap, b3);
            }
        }
        __syncthreads();
    }

    // per-thread column base and attention fragments (8 cols, one head)
    int cb = col0 + tx * 8;
    int head = cb / 64;              // global head of this 8-col fragment
    float fs[8], fd[8];
#pragma unroll
    for (int j = 0; j < 8; j++) {
        fs[j] = __ldg(&att_src[cb + j]);
        fd[j] = __ldg(&att_dst[cb + j]);
    }
    int lane = tid & 31;

#pragma unroll
    for (int m = 0; m < 8; m++) {
        int row = row0 + ty * 8 + m;
        bool valid = (row < M);
        float ps = 0.f, pd = 0.f;
        if (valid) {
            unsigned long long* cp = (unsigned long long*)&C[(size_t)row * N + cb];
#pragma unroll
            for (int nn = 0; nn < 4; nn++) {
                float lo, hi;
                unpack2(acc[m][nn], lo, hi);
                cp[nn] = acc[m][nn];
                ps += lo * fs[2 * nn] + hi * fs[2 * nn + 1];
                pd += lo * fd[2 * nn] + hi * fd[2 * nn + 1];
            }
        }
        // reduce over the 8 lanes that share one head (lane bits 0..2)
#pragma unroll
        for (int o = 4; o; o >>= 1) {
            ps += __shfl_xor_sync(0xFFFFFFFFu, ps, o);
            pd += __shfl_xor_sync(0xFFFFFFFFu, pd, o);
        }
        if (valid && (lane & 7) == 0) {
            atomicAdd(&asrc[row * H + head], ps);
            atomicAdd(&adst[row * H + head], pd);
        }
    }
}

// ---------------------- fused GAT aggregation (gather-side, no atomics) ------
template <int H, int CH>
__global__ void gat_agg_kernel(const float* __restrict__ h,
                               const float* __restrict__ asrc,
                               const float* __restrict__ adst,
                               const float* __restrict__ bias,
                               float* __restrict__ out) {
    constexpr int PER = (H * CH) / 32;
    int node = (blockIdx.x * blockDim.x + threadIdx.x) >> 5;
    int lane = threadIdx.x & 31;
    if (node >= N_NODES) return;
    int r0 = g_rowptr[node], r1 = g_rowptr[node + 1];
    const int head = (lane * PER) / CH;

    float ad[H];
#pragma unroll
    for (int hh = 0; hh < H; hh++) ad[hh] = __ldg(&adst[node * H + hh]);

    float mx[H];
#pragma unroll
    for (int hh = 0; hh < H; hh++) {
        float v = __ldg(&asrc[node * H + hh]) + ad[hh];
        mx[hh] = v > 0.f ? v : NEG_SLOPE * v;
    }
    for (int i = r0 + lane; i < r1; i += 32) {
        int s = g_esrc[i];
#pragma unroll
        for (int hh = 0; hh < H; hh++) {
            float v = __ldg(&asrc[s * H + hh]) + ad[hh];
            v = v > 0.f ? v : NEG_SLOPE * v;
            mx[hh] = fmaxf(mx[hh], v);
        }
    }
#pragma unroll
    for (int hh = 0; hh < H; hh++)
#pragma unroll
        for (int o = 16; o; o >>= 1)
            mx[hh] = fmaxf(mx[hh], __shfl_xor_sync(0xFFFFFFFFu, mx[hh], o));

    float acc[PER];
#pragma unroll
    for (int j = 0; j < PER; j++) acc[j] = 0.f;
    float wsum = 0.f;
    float mh = mx[head];
    float adh = ad[head];

    {   // self loop
        float v = __ldg(&asrc[node * H + head]) + adh;
        v = v > 0.f ? v : NEG_SLOPE * v;
        float w = __expf(v - mh);
        wsum += w;
        const float* hp = h + (size_t)node * (H * CH) + lane * PER;
        if constexpr (PER == 8) {
            float4 a = *(const float4*)hp;
            float4 b = *(const float4*)(hp + 4);
            acc[0] += w * a.x; acc[1] += w * a.y; acc[2] += w * a.z; acc[3] += w * a.w;
            acc[4] += w * b.x; acc[5] += w * b.y; acc[6] += w * b.z; acc[7] += w * b.w;
        } else {
            float2 a = *(const float2*)hp;
            acc[0] += w * a.x; acc[1] += w * a.y;
        }
    }
    for (int i = r0; i < r1; i++) {
        int s = g_esrc[i];
        float v = __ldg(&asrc[s * H + head]) + adh;
        v = v > 0.f ? v : NEG_SLOPE * v;
        float w = __expf(v - mh);
        wsum += w;
        const float* hp = h + (size_t)s * (H * CH) + lane * PER;
        if constexpr (PER == 8) {
            float4 a = *(const float4*)hp;
            float4 b = *(const float4*)(hp + 4);
            acc[0] += w * a.x; acc[1] += w * a.y; acc[2] += w * a.z; acc[3] += w * a.w;
            acc[4] += w * b.x; acc[5] += w * b.y; acc[6] += w * b.z; acc[7] += w * b.w;
        } else {
            float2 a = *(const float2*)hp;
            acc[0] += w * a.x; acc[1] += w * a.y;
        }
    }

    float inv = 1.f / (wsum + 1e-16f);
    float* op = out + (size_t)node * (H * CH) + lane * PER;
#pragma unroll
    for (int j = 0; j < PER; j++) {
        float v = acc[j] * inv + __ldg(&bias[lane * PER + j]);
        op[j] = v > 0.f ? v : expm1f(v);
    }
}

// ---------------------- graph mean-pool accumulation -------------------------
__global__ void pool_kernel(const void* __restrict__ batch,
                            const float* __restrict__ feat) {
    int i = blockIdx.x * blockDim.x + threadIdx.x;
    if (i >= N_NODES * C2) return;
    int n = i / C2;
    int c = i - n * C2;
    int g = idx_at(batch, n);
    atomicAdd(&g_pool[g * C2 + c], feat[i]);
    if (c == 0) atomicAdd(&g_cnt[g], 1);
}

// ---------------------- final MLP (tiny) --------------------------------------
__global__ void mlp_kernel(const float* __restrict__ w1, const float* __restrict__ bb1,
                           const float* __restrict__ w2, const float* __restrict__ bb2,
                           float* __restrict__ outp) {
    __shared__ float ps[G_GRAPHS * C2];
    __shared__ float zs[G_GRAPHS * 128];
    for (int i = threadIdx.x; i < G_GRAPHS * C2; i += blockDim.x) {
        int g = i / C2;
        float c = (float)g_cnt[g];
        ps[i] = g_pool[i] / fmaxf(c, 1.f);
    }
    __syncthreads();
    int j = threadIdx.x;  // 0..127
    for (int g = 0; g < G_GRAPHS; g++) {
        float acc = bb1[j];
#pragma unroll 8
        for (int c = 0; c < C2; c++) acc += ps[g * C2 + c] * w1[c * 128 + j];
        zs[g * 128 + j] = fmaxf(acc, 0.f);
    }
    __syncthreads();
    if (threadIdx.x < G_GRAPHS) {
        int g = threadIdx.x;
        float acc = bb2[0];
#pragma unroll 8
        for (int k = 0; k < 128; k++) acc += zs[g * 128 + k] * w2[k];
        outp[g] = acc;
    }
}

// =============================================================================
extern "C" void kernel_launch(void* const* d_in, const int* in_sizes, int n_in,
                              void* d_out, int out_size) {
    const float *x = nullptr, *W1 = nullptr, *as1 = nullptr, *ad1 = nullptr, *b1 = nullptr;
    const float *W2 = nullptr, *as2 = nullptr, *ad2 = nullptr, *b2 = nullptr;
    const float *l1w = nullptr, *l1b = nullptr, *l2w = nullptr, *l2b = nullptr;
    const void *ei = nullptr, *batch = nullptr;
    int n256 = 0, n64 = 0, n128 = 0;
    for (int i = 0; i < n_in; i++) {
        const void* p = d_in[i];
        switch (in_sizes[i]) {
            case 6400000: x = (const float*)p; break;
            case 1600000: ei = p; break;
            case 50000:   batch = p; break;
            case 32768:   W1 = (const float*)p; break;
            case 16384:   W2 = (const float*)p; break;
            case 8192:    l1w = (const float*)p; break;
            case 1:       l2b = (const float*)p; break;
            case 256:
                if (n256 == 0) as1 = (const float*)p;
                else if (n256 == 1) ad1 = (const float*)p;
                else b1 = (const float*)p;
                n256++;
                break;
            case 64:
                if (n64 == 0) as2 = (const float*)p;
                else if (n64 == 1) ad2 = (const float*)p;
                else b2 = (const float*)p;
                n64++;
                break;
            case 128:
                if (n128 == 0) l1b = (const float*)p;
                else l2w = (const float*)p;
                n128++;
                break;
            default: break;
        }
    }
    float* outp = (float*)d_out;

    float* h1;    cudaGetSymbolAddress((void**)&h1, g_h1);
    float* out1;  cudaGetSymbolAddress((void**)&out1, g_out1);
    float* h2;    cudaGetSymbolAddress((void**)&h2, g_h2);
    float* out2;  cudaGetSymbolAddress((void**)&out2, g_out2);
    float* asr1;  cudaGetSymbolAddress((void**)&asr1, g_asrc1);
    float* ads1;  cudaGetSymbolAddress((void**)&ads1, g_adst1);
    float* asr2;  cudaGetSymbolAddress((void**)&asr2, g_asrc2);
    float* ads2;  cudaGetSymbolAddress((void**)&ads2, g_adst2);

    const int BT = 256;
    int eb = (E_EDGES + BT - 1) / BT;

    // launch order chosen so gemm1 is launch index 3 (profiled by ncu)
    clear_kernel<<<512, BT>>>(ei);                    // 0 (includes dtype detect)
    count_kernel<<<eb, BT>>>(ei);                     // 1
    scan1_kernel<<<NB_SCAN, 256>>>();                 // 2
    {                                                 // 3: gemm1 + fused alpha1
        dim3 grid(C1 / 128, (N_NODES + 127) / 128);
        gemm_kernel<128, H1><<<grid, 256>>>(x, W1, h1, N_NODES, C1, 128,
                                            as1, ad1, asr1, ads1);
    }
    scan2_kernel<<<1, 256>>>();                       // 4
    scan3_kernel<<<NB_SCAN, 256>>>();                 // 5
    fill_kernel<<<eb, BT>>>(ei);                      // 6

    int blocks = (N_NODES * 32 + BT - 1) / BT;
    gat_agg_kernel<H1, 64><<<blocks, BT>>>(h1, asr1, ads1, b1, out1);   // 7
    {                                                 // 8: gemm2 + fused alpha2
        dim3 grid(1, (N_NODES + 127) / 128);
        gemm_kernel<64, 1><<<grid, 128>>>(out1, W2, h2, N_NODES, C2, 256,
                                          as2, ad2, asr2, ads2);
    }
    gat_agg_kernel<1, 64><<<blocks, BT>>>(h2, asr2, ads2, b2, out2);    // 9

    int n = N_NODES * C2;
    pool_kernel<<<(n + BT - 1) / BT, BT>>>(batch, out2);                // 10
    mlp_kernel<<<1, 128>>>(l1w, l1b, l2w, l2b, outp);                   // 11
}

// round 6
// speedup vs baseline: 2.4957x; 1.0300x over previous
#include <cuda_runtime.h>
#include <cstdint>

// Problem constants (fixed by reference)
#define N_NODES 50000
#define E_EDGES 800000
#define G_GRAPHS 64
#define C1 256           // HEADS*HID after layer 1
#define C2 64            // HID after layer 2
#define H1 4             // heads layer 1
#define NEG_SLOPE 0.2f
#define NB_SCAN ((N_NODES + 255) / 256)   // 196 scan blocks

// ------------------------- device scratch (no allocs allowed) ---------------
__device__ float g_h1[N_NODES * C1];
__device__ float g_out1[N_NODES * C1];
__device__ float g_h2[N_NODES * C2];
__device__ float g_out2[N_NODES * C2];
__device__ float g_asrc1[N_NODES * H1];
__device__ float g_adst1[N_NODES * H1];
__device__ float g_asrc2[N_NODES];
__device__ float g_adst2[N_NODES];
__device__ float g_pool[G_GRAPHS * C2];
__device__ int   g_cnt[G_GRAPHS];
__device__ int   g_is64;
// CSR by destination
__device__ int g_deg[N_NODES];
__device__ int g_fill[N_NODES];
__device__ int g_rowptr[N_NODES + 1];
__device__ int g_esrc[E_EDGES];
__device__ int g_bsum[NB_SCAN];

// ---------------------- helpers ---------------------------------------------
__device__ __forceinline__ int idx_at(const void* __restrict__ p, int i) {
    if (g_is64) return (int)((const long long*)p)[i];
    return ((const int*)p)[i];
}
__device__ __forceinline__ unsigned long long pack2(float lo, float hi) {
    unsigned long long r;
    asm("mov.b64 %0, {%1, %2};" : "=l"(r) : "f"(lo), "f"(hi));
    return r;
}
__device__ __forceinline__ void unpack2(unsigned long long v, float& lo, float& hi) {
    asm("mov.b64 {%0, %1}, %2;" : "=f"(lo), "=f"(hi) : "l"(v));
}
__device__ __forceinline__ void fma2(unsigned long long& d, unsigned long long a,
                                     unsigned long long b) {
    asm("fma.rn.f32x2 %0, %1, %2, %0;" : "+l"(d) : "l"(a), "l"(b));
}

// ---------------------- clear + dtype detection ------------------------------
__global__ void clear_kernel(const void* __restrict__ ei) {
    int stride = gridDim.x * blockDim.x;
    int gid = blockIdx.x * blockDim.x + threadIdx.x;
    if (gid == 0) {
        const long long* p = (const long long*)ei;
        int ok64 = 1;
        for (int i = 0; i < 64; i++) {
            long long v = p[i];
            if (v < 0 || v >= N_NODES) { ok64 = 0; break; }
        }
        g_is64 = ok64;
    }
    for (int i = gid; i < N_NODES; i += stride) { g_deg[i] = 0; g_fill[i] = 0; }
    for (int i = gid; i < N_NODES * H1; i += stride) { g_asrc1[i] = 0.f; g_adst1[i] = 0.f; }
    for (int i = gid; i < N_NODES; i += stride) { g_asrc2[i] = 0.f; g_adst2[i] = 0.f; }
    for (int i = gid; i < G_GRAPHS * C2; i += stride) g_pool[i] = 0.f;
    for (int i = gid; i < G_GRAPHS; i += stride) g_cnt[i] = 0;
}

// ---------------------- CSR build --------------------------------------------
__global__ void count_kernel(const void* __restrict__ ei) {
    int e = blockIdx.x * blockDim.x + threadIdx.x;
    if (e >= E_EDGES) return;
    int d = idx_at(ei, E_EDGES + e);
    atomicAdd(&g_deg[d], 1);
}

__global__ void scan1_kernel() {
    __shared__ int sh[256];
    int i = blockIdx.x * 256 + threadIdx.x;
    sh[threadIdx.x] = (i < N_NODES) ? g_deg[i] : 0;
    __syncthreads();
    for (int off = 128; off; off >>= 1) {
        if (threadIdx.x < off) sh[threadIdx.x] += sh[threadIdx.x + off];
        __syncthreads();
    }
    if (threadIdx.x == 0) g_bsum[blockIdx.x] = sh[0];
}
__global__ void scan2_kernel() {
    __shared__ int sh[256];
    int t = threadIdx.x;
    sh[t] = (t < NB_SCAN) ? g_bsum[t] : 0;
    __syncthreads();
    for (int off = 1; off < 256; off <<= 1) {
        int v = (t >= off) ? sh[t - off] : 0;
        __syncthreads();
        sh[t] += v;
        __syncthreads();
    }
    if (t < NB_SCAN) g_bsum[t] = sh[t];
}
__global__ void scan3_kernel() {
    __shared__ int sh[256];
    int t = threadIdx.x;
    int i = blockIdx.x * 256 + t;
    int v = (i < N_NODES) ? g_deg[i] : 0;
    sh[t] = v;
    __syncthreads();
    for (int off = 1; off < 256; off <<= 1) {
        int u = (t >= off) ? sh[t - off] : 0;
        __syncthreads();
        sh[t] += u;
        __syncthreads();
    }
    int base = blockIdx.x ? g_bsum[blockIdx.x - 1] : 0;
    if (i < N_NODES) g_rowptr[i] = base + sh[t] - v;
    if (i == N_NODES - 1) g_rowptr[N_NODES] = base + sh[t];
}

__global__ void fill_kernel(const void* __restrict__ ei) {
    int e = blockIdx.x * blockDim.x + threadIdx.x;
    if (e >= E_EDGES) return;
    int s = idx_at(ei, e);
    int d = idx_at(ei, E_EDGES + e);
    int slot = g_rowptr[d] + atomicAdd(&g_fill[d], 1);
    g_esrc[slot] = s;
}

// ---------------------- GEMM + fused alpha epilogue --------------------------
// BM=128, BK=16, 8x8 micro-tile, packed f32x2 accumulation, double-buffered
// smem with register-staged prefetch (1 sync per k-chunk, global latency
// hidden behind compute).
template <int BN, int H>
__global__ void gemm_kernel(const float* __restrict__ A, const float* __restrict__ B,
                            float* __restrict__ C, int M, int N, int K,
                            const float* __restrict__ att_src,
                            const float* __restrict__ att_dst,
                            float* __restrict__ asrc, float* __restrict__ adst) {
    constexpr int BM = 128, BK = 16;
    constexpr int NT = 16 * (BN / 8);
    constexpr int AREG = (BM * BK / 4) / NT;   // float4 per thread (A tile)
    constexpr int BREG = (BK * BN / 4) / NT;   // float4 per thread (B tile)
    __shared__ float As[2][BK][BM + 4];
    __shared__ float Bs[2][BK][BN];

    int tid = threadIdx.x;
    int tx = tid % (BN / 8);
    int ty = tid / (BN / 8);
    int row0 = blockIdx.y * BM, col0 = blockIdx.x * BN;

    float4 ar[AREG], br[BREG];

    auto loadA = [&](int k0) {
#pragma unroll
        for (int i = 0; i < AREG; i++) {
            int f = tid + i * NT;
            int r = f / (BK / 4);
            int rr = row0 + r;
            int c4 = f % (BK / 4);
            ar[i] = make_float4(0.f, 0.f, 0.f, 0.f);
            if (rr < M) ar[i] = *(const float4*)&A[(size_t)rr * K + k0 + c4 * 4];
        }
    };
    auto storeA = [&](int buf) {
#pragma unroll
        for (int i = 0; i < AREG; i++) {
            int f = tid + i * NT;
            int r = f / (BK / 4);
            int c4 = f % (BK / 4);
            As[buf][c4 * 4 + 0][r] = ar[i].x;
            As[buf][c4 * 4 + 1][r] = ar[i].y;
            As[buf][c4 * 4 + 2][r] = ar[i].z;
            As[buf][c4 * 4 + 3][r] = ar[i].w;
        }
    };
    auto loadB = [&](int k0) {
#pragma unroll
        for (int i = 0; i < BREG; i++) {
            int f = tid + i * NT;
            int r = f / (BN / 4);
            int c4 = f % (BN / 4);
            br[i] = *(const float4*)&B[(size_t)(k0 + r) * N + col0 + c4 * 4];
        }
    };
    auto storeB = [&](int buf) {
#pragma unroll
        for (int i = 0; i < BREG; i++) {
            int f = tid + i * NT;
            int r = f / (BN / 4);
            int c4 = f % (BN / 4);
            *(float4*)&Bs[buf][r][c4 * 4] = br[i];
        }
    };

    unsigned long long acc[8][4];
#pragma unroll
    for (int m = 0; m < 8; m++)
#pragma unroll
        for (int nn = 0; nn < 4; nn++) acc[m][nn] = 0ULL;

    const int NC = K / BK;
    loadA(0); loadB(0);
    storeA(0); storeB(0);
    __syncthreads();

    for (int c = 0; c < NC; c++) {
        int buf = c & 1;
        if (c + 1 < NC) { loadA((c + 1) * BK); loadB((c + 1) * BK); }
#pragma unroll
        for (int k = 0; k < BK; k++) {
            float4 a0 = *(const float4*)&As[buf][k][ty * 8];
            float4 a1 = *(const float4*)&As[buf][k][ty * 8 + 4];
            const unsigned long long* bp = (const unsigned long long*)&Bs[buf][k][tx * 8];
            unsigned long long b0 = bp[0], b1 = bp[1], b2 = bp[2], b3 = bp[3];
            float am[8] = {a0.x, a0.y, a0.z, a0.w, a1.x, a1.y, a1.z, a1.w};
#pragma unroll
            for (int m = 0; m < 8; m++) {
                unsigned long long ap = pack2(am[m], am[m]);
                fma2(acc[m][0], ap, b0);
                fma2(acc[m][1], ap, b1);
                fma2(acc[m][2], ap, b2);
                fma2(acc[m][3], ap, b3);
            }
        }
        if (c + 1 < NC) { storeA(buf ^ 1); storeB(buf ^ 1); }
        __syncthreads();
    }

    // epilogue: store C + fused attention partial dots
    int cb = col0 + tx * 8;
    int head = cb / 64;
    float fs[8], fd[8];
#pragma unroll
    for (int j = 0; j < 8; j++) {
        fs[j] = __ldg(&att_src[cb + j]);
        fd[j] = __ldg(&att_dst[cb + j]);
    }
    int lane = tid & 31;

#pragma unroll
    for (int m = 0; m < 8; m++) {
        int row = row0 + ty * 8 + m;
        bool valid = (row < M);
        float ps = 0.f, pd = 0.f;
        if (valid) {
            unsigned long long* cp = (unsigned long long*)&C[(size_t)row * N + cb];
#pragma unroll
            for (int nn = 0; nn < 4; nn++) {
                float lo, hi;
                unpack2(acc[m][nn], lo, hi);
                cp[nn] = acc[m][nn];
                ps += lo * fs[2 * nn] + hi * fs[2 * nn + 1];
                pd += lo * fd[2 * nn] + hi * fd[2 * nn + 1];
            }
        }
#pragma unroll
        for (int o = 4; o; o >>= 1) {
            ps += __shfl_xor_sync(0xFFFFFFFFu, ps, o);
            pd += __shfl_xor_sync(0xFFFFFFFFu, pd, o);
        }
        if (valid && (lane & 7) == 0) {
            atomicAdd(&asrc[row * H + head], ps);
            atomicAdd(&adst[row * H + head], pd);
        }
    }
}

// ---------------------- fused GAT aggregation (gather-side, no atomics) ------
template <int H, int CH>
__global__ void gat_agg_kernel(const float* __restrict__ h,
                               const float* __restrict__ asrc,
                               const float* __restrict__ adst,
                               const float* __restrict__ bias,
                               float* __restrict__ out) {
    constexpr int PER = (H * CH) / 32;
    int node = (blockIdx.x * blockDim.x + threadIdx.x) >> 5;
    int lane = threadIdx.x & 31;
    if (node >= N_NODES) return;
    int r0 = g_rowptr[node], r1 = g_rowptr[node + 1];
    const int head = (lane * PER) / CH;

    float ad[H];
#pragma unroll
    for (int hh = 0; hh < H; hh++) ad[hh] = __ldg(&adst[node * H + hh]);

    float mx[H];
#pragma unroll
    for (int hh = 0; hh < H; hh++) {
        float v = __ldg(&asrc[node * H + hh]) + ad[hh];
        mx[hh] = v > 0.f ? v : NEG_SLOPE * v;
    }
    for (int i = r0 + lane; i < r1; i += 32) {
        int s = g_esrc[i];
#pragma unroll
        for (int hh = 0; hh < H; hh++) {
            float v = __ldg(&asrc[s * H + hh]) + ad[hh];
            v = v > 0.f ? v : NEG_SLOPE * v;
            mx[hh] = fmaxf(mx[hh], v);
        }
    }
#pragma unroll
    for (int hh = 0; hh < H; hh++)
#pragma unroll
        for (int o = 16; o; o >>= 1)
            mx[hh] = fmaxf(mx[hh], __shfl_xor_sync(0xFFFFFFFFu, mx[hh], o));

    float acc[PER];
#pragma unroll
    for (int j = 0; j < PER; j++) acc[j] = 0.f;
    float wsum = 0.f;
    float mh = mx[head];
    float adh = ad[head];

    {   // self loop
        float v = __ldg(&asrc[node * H + head]) + adh;
        v = v > 0.f ? v : NEG_SLOPE * v;
        float w = __expf(v - mh);
        wsum += w;
        const float* hp = h + (size_t)node * (H * CH) + lane * PER;
        if constexpr (PER == 8) {
            float4 a = *(const float4*)hp;
            float4 b = *(const float4*)(hp + 4);
            acc[0] += w * a.x; acc[1] += w * a.y; acc[2] += w * a.z; acc[3] += w * a.w;
            acc[4] += w * b.x; acc[5] += w * b.y; acc[6] += w * b.z; acc[7] += w * b.w;
        } else {
            float2 a = *(const float2*)hp;
            acc[0] += w * a.x; acc[1] += w * a.y;
        }
    }
    for (int i = r0; i < r1; i++) {
        int s = g_esrc[i];
        float v = __ldg(&asrc[s * H + head]) + adh;
        v = v > 0.f ? v : NEG_SLOPE * v;
        float w = __expf(v - mh);
        wsum += w;
        const float* hp = h + (size_t)s * (H * CH) + lane * PER;
        if constexpr (PER == 8) {
            float4 a = *(const float4*)hp;
            float4 b = *(const float4*)(hp + 4);
            acc[0] += w * a.x; acc[1] += w * a.y; acc[2] += w * a.z; acc[3] += w * a.w;
            acc[4] += w * b.x; acc[5] += w * b.y; acc[6] += w * b.z; acc[7] += w * b.w;
        } else {
            float2 a = *(const float2*)hp;
            acc[0] += w * a.x; acc[1] += w * a.y;
        }
    }

    float inv = 1.f / (wsum + 1e-16f);
    float* op = out + (size_t)node * (H * CH) + lane * PER;
#pragma unroll
    for (int j = 0; j < PER; j++) {
        float v = acc[j] * inv + __ldg(&bias[lane * PER + j]);
        op[j] = v > 0.f ? v : expm1f(v);
    }
}

// ---------------------- graph mean-pool accumulation -------------------------
__global__ void pool_kernel(const void* __restrict__ batch,
                            const float* __restrict__ feat) {
    int i = blockIdx.x * blockDim.x + threadIdx.x;
    if (i >= N_NODES * C2) return;
    int n = i / C2;
    int c = i - n * C2;
    int g = idx_at(batch, n);
    atomicAdd(&g_pool[g * C2 + c], feat[i]);
    if (c == 0) atomicAdd(&g_cnt[g], 1);
}

// ---------------------- final MLP (tiny) --------------------------------------
__global__ void mlp_kernel(const float* __restrict__ w1, const float* __restrict__ bb1,
                           const float* __restrict__ w2, const float* __restrict__ bb2,
                           float* __restrict__ outp) {
    __shared__ float ps[G_GRAPHS * C2];
    __shared__ float zs[G_GRAPHS * 128];
    for (int i = threadIdx.x; i < G_GRAPHS * C2; i += blockDim.x) {
        int g = i / C2;
        float c = (float)g_cnt[g];
        ps[i] = g_pool[i] / fmaxf(c, 1.f);
    }
    __syncthreads();
    int j = threadIdx.x;
    for (int g = 0; g < G_GRAPHS; g++) {
        float acc = bb1[j];
#pragma unroll 8
        for (int c = 0; c < C2; c++) acc += ps[g * C2 + c] * w1[c * 128 + j];
        zs[g * 128 + j] = fmaxf(acc, 0.f);
    }
    __syncthreads();
    if (threadIdx.x < G_GRAPHS) {
        int g = threadIdx.x;
        float acc = bb2[0];
#pragma unroll 8
        for (int k = 0; k < 128; k++) acc += zs[g * 128 + k] * w2[k];
        outp[g] = acc;
    }
}

// =============================================================================
extern "C" void kernel_launch(void* const* d_in, const int* in_sizes, int n_in,
                              void* d_out, int out_size) {
    const float *x = nullptr, *W1 = nullptr, *as1 = nullptr, *ad1 = nullptr, *b1 = nullptr;
    const float *W2 = nullptr, *as2 = nullptr, *ad2 = nullptr, *b2 = nullptr;
    const float *l1w = nullptr, *l1b = nullptr, *l2w = nullptr, *l2b = nullptr;
    const void *ei = nullptr, *batch = nullptr;
    int n256 = 0, n64 = 0, n128 = 0;
    for (int i = 0; i < n_in; i++) {
        const void* p = d_in[i];
        switch (in_sizes[i]) {
            case 6400000: x = (const float*)p; break;
            case 1600000: ei = p; break;
            case 50000:   batch = p; break;
            case 32768:   W1 = (const float*)p; break;
            case 16384:   W2 = (const float*)p; break;
            case 8192:    l1w = (const float*)p; break;
            case 1:       l2b = (const float*)p; break;
            case 256:
                if (n256 == 0) as1 = (const float*)p;
                else if (n256 == 1) ad1 = (const float*)p;
                else b1 = (const float*)p;
                n256++;
                break;
            case 64:
                if (n64 == 0) as2 = (const float*)p;
                else if (n64 == 1) ad2 = (const float*)p;
                else b2 = (const float*)p;
                n64++;
                break;
            case 128:
                if (n128 == 0) l1b = (const float*)p;
                else l2w = (const float*)p;
                n128++;
                break;
            default: break;
        }
    }
    float* outp = (float*)d_out;

    float* h1;    cudaGetSymbolAddress((void**)&h1, g_h1);
    float* out1;  cudaGetSymbolAddress((void**)&out1, g_out1);
    float* h2;    cudaGetSymbolAddress((void**)&h2, g_h2);
    float* out2;  cudaGetSymbolAddress((void**)&out2, g_out2);
    float* asr1;  cudaGetSymbolAddress((void**)&asr1, g_asrc1);
    float* ads1;  cudaGetSymbolAddress((void**)&ads1, g_adst1);
    float* asr2;  cudaGetSymbolAddress((void**)&asr2, g_asrc2);
    float* ads2;  cudaGetSymbolAddress((void**)&ads2, g_adst2);

    const int BT = 256;
    int eb = (E_EDGES + BT - 1) / BT;

    // launch order keeps gemm1 at launch index 3 (ncu profiles it)
    clear_kernel<<<512, BT>>>(ei);                    // 0
    count_kernel<<<eb, BT>>>(ei);                     // 1
    scan1_kernel<<<NB_SCAN, 256>>>();                 // 2
    {                                                 // 3: gemm1 + fused alpha1
        dim3 grid(C1 / 128, (N_NODES + 127) / 128);
        gemm_kernel<128, H1><<<grid, 256>>>(x, W1, h1, N_NODES, C1, 128,
                                            as1, ad1, asr1, ads1);
    }
    scan2_kernel<<<1, 256>>>();                       // 4
    scan3_kernel<<<NB_SCAN, 256>>>();                 // 5
    fill_kernel<<<eb, BT>>>(ei);                      // 6

    int blocks = (N_NODES * 32 + BT - 1) / BT;
    gat_agg_kernel<H1, 64><<<blocks, BT>>>(h1, asr1, ads1, b1, out1);   // 7
    {                                                 // 8: gemm2 + fused alpha2
        dim3 grid(1, (N_NODES + 127) / 128);
        gemm_kernel<64, 1><<<grid, 128>>>(out1, W2, h2, N_NODES, C2, 256,
                                          as2, ad2, asr2, ads2);
    }
    gat_agg_kernel<1, 64><<<blocks, BT>>>(h2, asr2, ads2, b2, out2);    // 9

    int n = N_NODES * C2;
    pool_kernel<<<(n + BT - 1) / BT, BT>>>(batch, out2);                // 10
    mlp_kernel<<<1, 128>>>(l1w, l1b, l2w, l2b, outp);                   // 11
}

// round 7
// speedup vs baseline: 2.7132x; 1.0871x over previous
#include <cuda_runtime.h>
#include <cuda_bf16.h>
#include <cstdint>

// Problem constants (fixed by reference)
#define N_NODES 50000
#define E_EDGES 800000
#define G_GRAPHS 64
#define C1 256           // HEADS*HID after layer 1
#define C2 64            // HID after layer 2
#define H1 4             // heads layer 1
#define NEG_SLOPE 0.2f
#define NB_SCAN ((N_NODES + 255) / 256)

// ------------------------- device scratch (no allocs allowed) ---------------
__device__ __nv_bfloat16 g_h1b[N_NODES * C1];   // bf16 copy of x@W1 (gather src)
__device__ __nv_bfloat16 g_h2b[N_NODES * C2];   // bf16 copy of out1@W2
__device__ float g_out1[N_NODES * C1];
__device__ float g_out2[N_NODES * C2];
__device__ float g_asrc1[N_NODES * H1];
__device__ float g_adst1[N_NODES * H1];
__device__ float g_asrc2[N_NODES];
__device__ float g_adst2[N_NODES];
__device__ float g_pool[G_GRAPHS * C2];
__device__ int   g_cnt[G_GRAPHS];
__device__ int   g_is64;
// CSR by destination
__device__ int g_deg[N_NODES];
__device__ int g_fill[N_NODES];
__device__ int g_rowptr[N_NODES + 1];
__device__ int g_esrc[E_EDGES];
__device__ int g_bsum[NB_SCAN];

// ---------------------- helpers ---------------------------------------------
__device__ __forceinline__ int idx_at(const void* __restrict__ p, int i) {
    if (g_is64) return (int)((const long long*)p)[i];
    return ((const int*)p)[i];
}
__device__ __forceinline__ unsigned long long pack2(float lo, float hi) {
    unsigned long long r;
    asm("mov.b64 %0, {%1, %2};" : "=l"(r) : "f"(lo), "f"(hi));
    return r;
}
__device__ __forceinline__ void unpack2(unsigned long long v, float& lo, float& hi) {
    asm("mov.b64 {%0, %1}, %2;" : "=f"(lo), "=f"(hi) : "l"(v));
}
__device__ __forceinline__ void fma2(unsigned long long& d, unsigned long long a,
                                     unsigned long long b) {
    asm("fma.rn.f32x2 %0, %1, %2, %0;" : "+l"(d) : "l"(a), "l"(b));
}
// pack (lo,hi) floats into bf16x2 (lo in low half)
__device__ __forceinline__ unsigned bf16x2_of(float lo, float hi) {
    unsigned r;
    asm("cvt.rn.bf16x2.f32 %0, %1, %2;" : "=r"(r) : "f"(hi), "f"(lo));
    return r;
}
__device__ __forceinline__ float2 bf2f(unsigned v) {
    return __bfloat1622float2(*reinterpret_cast<const __nv_bfloat162*>(&v));
}

// ---------------------- clear + dtype detection ------------------------------
__global__ void clear_kernel(const void* __restrict__ ei) {
    int stride = gridDim.x * blockDim.x;
    int gid = blockIdx.x * blockDim.x + threadIdx.x;
    if (gid == 0) {
        const long long* p = (const long long*)ei;
        int ok64 = 1;
        for (int i = 0; i < 64; i++) {
            long long v = p[i];
            if (v < 0 || v >= N_NODES) { ok64 = 0; break; }
        }
        g_is64 = ok64;
    }
    for (int i = gid; i < N_NODES; i += stride) { g_deg[i] = 0; g_fill[i] = 0; }
    for (int i = gid; i < N_NODES * H1; i += stride) { g_asrc1[i] = 0.f; g_adst1[i] = 0.f; }
    for (int i = gid; i < N_NODES; i += stride) { g_asrc2[i] = 0.f; g_adst2[i] = 0.f; }
    for (int i = gid; i < G_GRAPHS * C2; i += stride) g_pool[i] = 0.f;
    for (int i = gid; i < G_GRAPHS; i += stride) g_cnt[i] = 0;
}

// ---------------------- CSR build --------------------------------------------
__global__ void count_kernel(const void* __restrict__ ei) {
    int e = blockIdx.x * blockDim.x + threadIdx.x;
    if (e >= E_EDGES) return;
    int d = idx_at(ei, E_EDGES + e);
    atomicAdd(&g_deg[d], 1);
}

__global__ void scan1_kernel() {
    __shared__ int sh[256];
    int i = blockIdx.x * 256 + threadIdx.x;
    sh[threadIdx.x] = (i < N_NODES) ? g_deg[i] : 0;
    __syncthreads();
    for (int off = 128; off; off >>= 1) {
        if (threadIdx.x < off) sh[threadIdx.x] += sh[threadIdx.x + off];
        __syncthreads();
    }
    if (threadIdx.x == 0) g_bsum[blockIdx.x] = sh[0];
}
__global__ void scan2_kernel() {
    __shared__ int sh[256];
    int t = threadIdx.x;
    sh[t] = (t < NB_SCAN) ? g_bsum[t] : 0;
    __syncthreads();
    for (int off = 1; off < 256; off <<= 1) {
        int v = (t >= off) ? sh[t - off] : 0;
        __syncthreads();
        sh[t] += v;
        __syncthreads();
    }
    if (t < NB_SCAN) g_bsum[t] = sh[t];
}
__global__ void scan3_kernel() {
    __shared__ int sh[256];
    int t = threadIdx.x;
    int i = blockIdx.x * 256 + t;
    int v = (i < N_NODES) ? g_deg[i] : 0;
    sh[t] = v;
    __syncthreads();
    for (int off = 1; off < 256; off <<= 1) {
        int u = (t >= off) ? sh[t - off] : 0;
        __syncthreads();
        sh[t] += u;
        __syncthreads();
    }
    int base = blockIdx.x ? g_bsum[blockIdx.x - 1] : 0;
    if (i < N_NODES) g_rowptr[i] = base + sh[t] - v;
    if (i == N_NODES - 1) g_rowptr[N_NODES] = base + sh[t];
}

__global__ void fill_kernel(const void* __restrict__ ei) {
    int e = blockIdx.x * blockDim.x + threadIdx.x;
    if (e >= E_EDGES) return;
    int s = idx_at(ei, e);
    int d = idx_at(ei, E_EDGES + e);
    int slot = g_rowptr[d] + atomicAdd(&g_fill[d], 1);
    g_esrc[slot] = s;
}

// ---------------------- GEMM + fused alpha epilogue --------------------------
// BM=128, BK=16, 8x8 micro-tile, packed f32x2 accumulation (R5 single-buffer
// mainloop). Epilogue: stores bf16 output ONLY (gather source) and computes
// fused attention logits into asrc/adst via 8-lane shfl + atomicAdd.
template <int BN, int H>
__global__ void gemm_kernel(const float* __restrict__ A, const float* __restrict__ B,
                            __nv_bfloat16* __restrict__ Cb, int M, int N, int K,
                            const float* __restrict__ att_src,
                            const float* __restrict__ att_dst,
                            float* __restrict__ asrc, float* __restrict__ adst) {
    constexpr int BM = 128, BK = 16;
    constexpr int NT = 16 * (BN / 8);
    __shared__ float As[BK][BM + 4];
    __shared__ float Bs[BK][BN];

    int tid = threadIdx.x;
    int tx = tid % (BN / 8);
    int ty = tid / (BN / 8);
    int row0 = blockIdx.y * BM, col0 = blockIdx.x * BN;

    unsigned long long acc[8][4];
#pragma unroll
    for (int m = 0; m < 8; m++)
#pragma unroll
        for (int nn = 0; nn < 4; nn++) acc[m][nn] = 0ULL;

    for (int k0 = 0; k0 < K; k0 += BK) {
        constexpr int A4 = BM * BK / 4;
#pragma unroll
        for (int f = tid; f < A4; f += NT) {
            int r = f / (BK / 4);
            int c4 = f % (BK / 4);
            int rr = row0 + r;
            float4 v = make_float4(0.f, 0.f, 0.f, 0.f);
            if (rr < M) v = *(const float4*)&A[(size_t)rr * K + k0 + c4 * 4];
            As[c4 * 4 + 0][r] = v.x;
            As[c4 * 4 + 1][r] = v.y;
            As[c4 * 4 + 2][r] = v.z;
            As[c4 * 4 + 3][r] = v.w;
        }
        constexpr int B4 = BK * BN / 4;
#pragma unroll
        for (int f = tid; f < B4; f += NT) {
            int r = f / (BN / 4);
            int c4 = f % (BN / 4);
            *(float4*)&Bs[r][c4 * 4] = *(const float4*)&B[(size_t)(k0 + r) * N + col0 + c4 * 4];
        }
        __syncthreads();
#pragma unroll
        for (int k = 0; k < BK; k++) {
            float4 a0 = *(const float4*)&As[k][ty * 8];
            float4 a1 = *(const float4*)&As[k][ty * 8 + 4];
            const unsigned long long* bp = (const unsigned long long*)&Bs[k][tx * 8];
            unsigned long long b0 = bp[0], b1 = bp[1], b2 = bp[2], b3 = bp[3];
            float am[8] = {a0.x, a0.y, a0.z, a0.w, a1.x, a1.y, a1.z, a1.w};
#pragma unroll
            for (int m = 0; m < 8; m++) {
                unsigned long long ap = pack2(am[m], am[m]);
                fma2(acc[m][0], ap, b0);
                fma2(acc[m][1], ap, b1);
                fma2(acc[m][2], ap, b2);
                fma2(acc[m][3], ap, b3);
            }
        }
        __syncthreads();
    }

    // epilogue: bf16 store + fused attention partial dots
    int cb = col0 + tx * 8;
    int head = cb / 64;
    float fs[8], fd[8];
#pragma unroll
    for (int j = 0; j < 8; j++) {
        fs[j] = __ldg(&att_src[cb + j]);
        fd[j] = __ldg(&att_dst[cb + j]);
    }
    int lane = tid & 31;

#pragma unroll
    for (int m = 0; m < 8; m++) {
        int row = row0 + ty * 8 + m;
        bool valid = (row < M);
        float ps = 0.f, pd = 0.f;
        if (valid) {
            unsigned r32[4];
#pragma unroll
            for (int nn = 0; nn < 4; nn++) {
                float lo, hi;
                unpack2(acc[m][nn], lo, hi);
                ps += lo * fs[2 * nn] + hi * fs[2 * nn + 1];
                pd += lo * fd[2 * nn] + hi * fd[2 * nn + 1];
                r32[nn] = bf16x2_of(lo, hi);
            }
            *(uint4*)&Cb[(size_t)row * N + cb] = make_uint4(r32[0], r32[1], r32[2], r32[3]);
        }
#pragma unroll
        for (int o = 4; o; o >>= 1) {
            ps += __shfl_xor_sync(0xFFFFFFFFu, ps, o);
            pd += __shfl_xor_sync(0xFFFFFFFFu, pd, o);
        }
        if (valid && (lane & 7) == 0) {
            atomicAdd(&asrc[row * H + head], ps);
            atomicAdd(&adst[row * H + head], pd);
        }
    }
}

// ---------------------- fused GAT aggregation (bf16 gather) ------------------
template <int H, int CH>
__global__ void gat_agg_kernel(const __nv_bfloat16* __restrict__ hb,
                               const float* __restrict__ asrc,
                               const float* __restrict__ adst,
                               const float* __restrict__ bias,
                               float* __restrict__ out) {
    constexpr int PER = (H * CH) / 32;
    int node = (blockIdx.x * blockDim.x + threadIdx.x) >> 5;
    int lane = threadIdx.x & 31;
    if (node >= N_NODES) return;
    int r0 = g_rowptr[node], r1 = g_rowptr[node + 1];
    const int head = (lane * PER) / CH;

    float ad[H];
#pragma unroll
    for (int hh = 0; hh < H; hh++) ad[hh] = __ldg(&adst[node * H + hh]);

    float mx[H];
#pragma unroll
    for (int hh = 0; hh < H; hh++) {
        float v = __ldg(&asrc[node * H + hh]) + ad[hh];
        mx[hh] = v > 0.f ? v : NEG_SLOPE * v;
    }
    for (int i = r0 + lane; i < r1; i += 32) {
        int s = g_esrc[i];
#pragma unroll
        for (int hh = 0; hh < H; hh++) {
            float v = __ldg(&asrc[s * H + hh]) + ad[hh];
            v = v > 0.f ? v : NEG_SLOPE * v;
            mx[hh] = fmaxf(mx[hh], v);
        }
    }
#pragma unroll
    for (int hh = 0; hh < H; hh++)
#pragma unroll
        for (int o = 16; o; o >>= 1)
            mx[hh] = fmaxf(mx[hh], __shfl_xor_sync(0xFFFFFFFFu, mx[hh], o));

    float acc[PER];
#pragma unroll
    for (int j = 0; j < PER; j++) acc[j] = 0.f;
    float wsum = 0.f;
    float mh = mx[head];
    float adh = ad[head];

    {   // self loop
        float v = __ldg(&asrc[node * H + head]) + adh;
        v = v > 0.f ? v : NEG_SLOPE * v;
        float w = __expf(v - mh);
        wsum += w;
        const __nv_bfloat16* hp = hb + (size_t)node * (H * CH) + lane * PER;
        if constexpr (PER == 8) {
            uint4 v4 = *(const uint4*)hp;
            float2 f0 = bf2f(v4.x), f1 = bf2f(v4.y), f2 = bf2f(v4.z), f3 = bf2f(v4.w);
            acc[0] += w * f0.x; acc[1] += w * f0.y; acc[2] += w * f1.x; acc[3] += w * f1.y;
            acc[4] += w * f2.x; acc[5] += w * f2.y; acc[6] += w * f3.x; acc[7] += w * f3.y;
        } else {
            float2 f = bf2f(*(const unsigned*)hp);
            acc[0] += w * f.x; acc[1] += w * f.y;
        }
    }
    for (int i = r0; i < r1; i++) {
        int s = g_esrc[i];
        float v = __ldg(&asrc[s * H + head]) + adh;
        v = v > 0.f ? v : NEG_SLOPE * v;
        float w = __expf(v - mh);
        wsum += w;
        const __nv_bfloat16* hp = hb + (size_t)s * (H * CH) + lane * PER;
        if constexpr (PER == 8) {
            uint4 v4 = *(const uint4*)hp;
            float2 f0 = bf2f(v4.x), f1 = bf2f(v4.y), f2 = bf2f(v4.z), f3 = bf2f(v4.w);
            acc[0] += w * f0.x; acc[1] += w * f0.y; acc[2] += w * f1.x; acc[3] += w * f1.y;
            acc[4] += w * f2.x; acc[5] += w * f2.y; acc[6] += w * f3.x; acc[7] += w * f3.y;
        } else {
            float2 f = bf2f(*(const unsigned*)hp);
            acc[0] += w * f.x; acc[1] += w * f.y;
        }
    }

    float inv = 1.f / (wsum + 1e-16f);
    float* op = out + (size_t)node * (H * CH) + lane * PER;
#pragma unroll
    for (int j = 0; j < PER; j++) {
        float v = acc[j] * inv + __ldg(&bias[lane * PER + j]);
        op[j] = v > 0.f ? v : expm1f(v);
    }
}

// ---------------------- graph mean-pool accumulation -------------------------
__global__ void pool_kernel(const void* __restrict__ batch,
                            const float* __restrict__ feat) {
    int i = blockIdx.x * blockDim.x + threadIdx.x;
    if (i >= N_NODES * C2) return;
    int n = i / C2;
    int c = i - n * C2;
    int g = idx_at(batch, n);
    atomicAdd(&g_pool[g * C2 + c], feat[i]);
    if (c == 0) atomicAdd(&g_cnt[g], 1);
}

// ---------------------- final MLP (tiny) --------------------------------------
__global__ void mlp_kernel(const float* __restrict__ w1, const float* __restrict__ bb1,
                           const float* __restrict__ w2, const float* __restrict__ bb2,
                           float* __restrict__ outp) {
    __shared__ float ps[G_GRAPHS * C2];
    __shared__ float zs[G_GRAPHS * 128];
    for (int i = threadIdx.x; i < G_GRAPHS * C2; i += blockDim.x) {
        int g = i / C2;
        float c = (float)g_cnt[g];
        ps[i] = g_pool[i] / fmaxf(c, 1.f);
    }
    __syncthreads();
    int j = threadIdx.x;
    for (int g = 0; g < G_GRAPHS; g++) {
        float acc = bb1[j];
#pragma unroll 8
        for (int c = 0; c < C2; c++) acc += ps[g * C2 + c] * w1[c * 128 + j];
        zs[g * 128 + j] = fmaxf(acc, 0.f);
    }
    __syncthreads();
    if (threadIdx.x < G_GRAPHS) {
        int g = threadIdx.x;
        float acc = bb2[0];
#pragma unroll 8
        for (int k = 0; k < 128; k++) acc += zs[g * 128 + k] * w2[k];
        outp[g] = acc;
    }
}

// =============================================================================
extern "C" void kernel_launch(void* const* d_in, const int* in_sizes, int n_in,
                              void* d_out, int out_size) {
    const float *x = nullptr, *W1 = nullptr, *as1 = nullptr, *ad1 = nullptr, *b1 = nullptr;
    const float *W2 = nullptr, *as2 = nullptr, *ad2 = nullptr, *b2 = nullptr;
    const float *l1w = nullptr, *l1b = nullptr, *l2w = nullptr, *l2b = nullptr;
    const void *ei = nullptr, *batch = nullptr;
    int n256 = 0, n64 = 0, n128 = 0;
    for (int i = 0; i < n_in; i++) {
        const void* p = d_in[i];
        switch (in_sizes[i]) {
            case 6400000: x = (const float*)p; break;
            case 1600000: ei = p; break;
            case 50000:   batch = p; break;
            case 32768:   W1 = (const float*)p; break;
            case 16384:   W2 = (const float*)p; break;
            case 8192:    l1w = (const float*)p; break;
            case 1:       l2b = (const float*)p; break;
            case 256:
                if (n256 == 0) as1 = (const float*)p;
                else if (n256 == 1) ad1 = (const float*)p;
                else b1 = (const float*)p;
                n256++;
                break;
            case 64:
                if (n64 == 0) as2 = (const float*)p;
                else if (n64 == 1) ad2 = (const float*)p;
                else b2 = (const float*)p;
                n64++;
                break;
            case 128:
                if (n128 == 0) l1b = (const float*)p;
                else l2w = (const float*)p;
                n128++;
                break;
            default: break;
        }
    }
    float* outp = (float*)d_out;

    __nv_bfloat16* h1b; cudaGetSymbolAddress((void**)&h1b, g_h1b);
    __nv_bfloat16* h2b; cudaGetSymbolAddress((void**)&h2b, g_h2b);
    float* out1;  cudaGetSymbolAddress((void**)&out1, g_out1);
    float* out2;  cudaGetSymbolAddress((void**)&out2, g_out2);
    float* asr1;  cudaGetSymbolAddress((void**)&asr1, g_asrc1);
    float* ads1;  cudaGetSymbolAddress((void**)&ads1, g_adst1);
    float* asr2;  cudaGetSymbolAddress((void**)&asr2, g_asrc2);
    float* ads2;  cudaGetSymbolAddress((void**)&ads2, g_adst2);

    const int BT = 256;
    int eb = (E_EDGES + BT - 1) / BT;

    // launch order keeps gemm1 at launch index 3 (ncu profiles it)
    clear_kernel<<<512, BT>>>(ei);                    // 0
    count_kernel<<<eb, BT>>>(ei);                     // 1
    scan1_kernel<<<NB_SCAN, 256>>>();                 // 2
    {                                                 // 3: gemm1 + fused alpha1
        dim3 grid(C1 / 128, (N_NODES + 127) / 128);
        gemm_kernel<128, H1><<<grid, 256>>>(x, W1, h1b, N_NODES, C1, 128,
                                            as1, ad1, asr1, ads1);
    }
    scan2_kernel<<<1, 256>>>();                       // 4
    scan3_kernel<<<NB_SCAN, 256>>>();                 // 5
    fill_kernel<<<eb, BT>>>(ei);                      // 6

    int blocks = (N_NODES * 32 + BT - 1) / BT;
    gat_agg_kernel<H1, 64><<<blocks, BT>>>(h1b, asr1, ads1, b1, out1);  // 7
    {                                                 // 8: gemm2 + fused alpha2
        dim3 grid(1, (N_NODES + 127) / 128);
        gemm_kernel<64, 1><<<grid, 128>>>(out1, W2, h2b, N_NODES, C2, 256,
                                          as2, ad2, asr2, ads2);
    }
    gat_agg_kernel<1, 64><<<blocks, BT>>>(h2b, asr2, ads2, b2, out2);   // 9

    int n = N_NODES * C2;
    pool_kernel<<<(n + BT - 1) / BT, BT>>>(batch, out2);                // 10
    mlp_kernel<<<1, 128>>>(l1w, l1b, l2w, l2b, outp);                   // 11
}

// round 9
// speedup vs baseline: 3.5542x; 1.3100x over previous
#include <cuda_runtime.h>
#include <cuda_bf16.h>
#include <cstdint>

// Problem constants (fixed by reference)
#define N_NODES 50000
#define E_EDGES 800000
#define G_GRAPHS 64
#define C1 256           // HEADS*HID after layer 1
#define C2 64            // HID after layer 2
#define H1 4             // heads layer 1
#define NEG_SLOPE 0.2f
#define NB_SCAN ((N_NODES + 255) / 256)

// ------------------------- device scratch (no allocs allowed) ---------------
__device__ __nv_bfloat16 g_h1b[N_NODES * C1];   // bf16 x@W1 (gather src)
__device__ __nv_bfloat16 g_h2b[N_NODES * C2];   // bf16 out1@W2
__device__ float g_out1[N_NODES * C1];
__device__ float g_out2[N_NODES * C2];
__device__ float g_asrc1[N_NODES * H1];
__device__ float g_adst1[N_NODES * H1];
__device__ float g_asrc2[N_NODES];
__device__ float g_adst2[N_NODES];
__device__ float g_pool[G_GRAPHS * C2];
__device__ int   g_cnt[G_GRAPHS];
__device__ int   g_is64;
// CSR by destination
__device__ int g_deg[N_NODES];
__device__ int g_fill[N_NODES];
__device__ int g_rowptr[N_NODES + 1];
__device__ int g_esrc[E_EDGES];
__device__ int g_bsum[NB_SCAN];

// ---------------------- helpers ---------------------------------------------
__device__ __forceinline__ int idx_at(const void* __restrict__ p, int i) {
    if (g_is64) return (int)((const long long*)p)[i];
    return ((const int*)p)[i];
}
__device__ __forceinline__ float2 bf2f(unsigned v) {
    return __bfloat1622float2(*reinterpret_cast<const __nv_bfloat162*>(&v));
}
__device__ __forceinline__ unsigned scvta(const void* p) {
    return (unsigned)__cvta_generic_to_shared(p);
}
__device__ __forceinline__ void ldsm_x4(unsigned& r0, unsigned& r1, unsigned& r2,
                                        unsigned& r3, unsigned addr) {
    asm volatile("ldmatrix.sync.aligned.m8n8.x4.shared.b16 {%0,%1,%2,%3}, [%4];"
                 : "=r"(r0), "=r"(r1), "=r"(r2), "=r"(r3) : "r"(addr) : "memory");
}
__device__ __forceinline__ void ldsm_x4_t(unsigned& r0, unsigned& r1, unsigned& r2,
                                          unsigned& r3, unsigned addr) {
    asm volatile("ldmatrix.sync.aligned.m8n8.x4.trans.shared.b16 {%0,%1,%2,%3}, [%4];"
                 : "=r"(r0), "=r"(r1), "=r"(r2), "=r"(r3) : "r"(addr) : "memory");
}
__device__ __forceinline__ void mma16816(float* c, const unsigned* a,
                                         unsigned b0, unsigned b1) {
    asm volatile(
        "mma.sync.aligned.m16n8k16.row.col.f32.bf16.bf16.f32 "
        "{%0,%1,%2,%3}, {%4,%5,%6,%7}, {%8,%9}, {%0,%1,%2,%3};"
        : "+f"(c[0]), "+f"(c[1]), "+f"(c[2]), "+f"(c[3])
        : "r"(a[0]), "r"(a[1]), "r"(a[2]), "r"(a[3]), "r"(b0), "r"(b1));
}
// split fp32 pair into (hi, lo) bf16x2 words; v ≈ hi + lo elementwise
__device__ __forceinline__ void split2(float x, float y, unsigned& hi, unsigned& lo) {
    __nv_bfloat16 hx = __float2bfloat16_rn(x);
    __nv_bfloat16 hy = __float2bfloat16_rn(y);
    __nv_bfloat16 lx = __float2bfloat16_rn(x - __bfloat162float(hx));
    __nv_bfloat16 ly = __float2bfloat16_rn(y - __bfloat162float(hy));
    __nv_bfloat162 h2 = __nv_bfloat162(hx, hy);
    __nv_bfloat162 l2 = __nv_bfloat162(lx, ly);
    memcpy(&hi, &h2, 4);
    memcpy(&lo, &l2, 4);
}

// ---------------------- clear + dtype detection ------------------------------
__global__ void clear_kernel(const void* __restrict__ ei) {
    int stride = gridDim.x * blockDim.x;
    int gid = blockIdx.x * blockDim.x + threadIdx.x;
    if (gid == 0) {
        const long long* p = (const long long*)ei;
        int ok64 = 1;
        for (int i = 0; i < 64; i++) {
            long long v = p[i];
            if (v < 0 || v >= N_NODES) { ok64 = 0; break; }
        }
        g_is64 = ok64;
    }
    for (int i = gid; i < N_NODES; i += stride) { g_deg[i] = 0; g_fill[i] = 0; }
    for (int i = gid; i < N_NODES * H1; i += stride) { g_asrc1[i] = 0.f; g_adst1[i] = 0.f; }
    for (int i = gid; i < N_NODES; i += stride) { g_asrc2[i] = 0.f; g_adst2[i] = 0.f; }
    for (int i = gid; i < G_GRAPHS * C2; i += stride) g_pool[i] = 0.f;
    for (int i = gid; i < G_GRAPHS; i += stride) g_cnt[i] = 0;
}

// ---------------------- CSR build --------------------------------------------
__global__ void count_kernel(const void* __restrict__ ei) {
    int e = blockIdx.x * blockDim.x + threadIdx.x;
    if (e >= E_EDGES) return;
    int d = idx_at(ei, E_EDGES + e);
    atomicAdd(&g_deg[d], 1);
}

__global__ void scan1_kernel() {
    __shared__ int sh[256];
    int i = blockIdx.x * 256 + threadIdx.x;
    sh[threadIdx.x] = (i < N_NODES) ? g_deg[i] : 0;
    __syncthreads();
    for (int off = 128; off; off >>= 1) {
        if (threadIdx.x < off) sh[threadIdx.x] += sh[threadIdx.x + off];
        __syncthreads();
    }
    if (threadIdx.x == 0) g_bsum[blockIdx.x] = sh[0];
}
__global__ void scan2_kernel() {
    __shared__ int sh[256];
    int t = threadIdx.x;
    sh[t] = (t < NB_SCAN) ? g_bsum[t] : 0;
    __syncthreads();
    for (int off = 1; off < 256; off <<= 1) {
        int v = (t >= off) ? sh[t - off] : 0;
        __syncthreads();
        sh[t] += v;
        __syncthreads();
    }
    if (t < NB_SCAN) g_bsum[t] = sh[t];
}
__global__ void scan3_kernel() {
    __shared__ int sh[256];
    int t = threadIdx.x;
    int i = blockIdx.x * 256 + t;
    int v = (i < N_NODES) ? g_deg[i] : 0;
    sh[t] = v;
    __syncthreads();
    for (int off = 1; off < 256; off <<= 1) {
        int u = (t >= off) ? sh[t - off] : 0;
        __syncthreads();
        sh[t] += u;
        __syncthreads();
    }
    int base = blockIdx.x ? g_bsum[blockIdx.x - 1] : 0;
    if (i < N_NODES) g_rowptr[i] = base + sh[t] - v;
    if (i == N_NODES - 1) g_rowptr[N_NODES] = base + sh[t];
}

__global__ void fill_kernel(const void* __restrict__ ei) {
    int e = blockIdx.x * blockDim.x + threadIdx.x;
    if (e >= E_EDGES) return;
    int s = idx_at(ei, e);
    int d = idx_at(ei, E_EDGES + e);
    int slot = g_rowptr[d] + atomicAdd(&g_fill[d], 1);
    g_esrc[slot] = s;
}

// ---------------------- bf16 tensor-core GEMM (split-B) + fused alpha --------
// C = A @ B with B split into hi+lo bf16 (kills coherent weight-rounding
// error); A bf16 (per-node rounding, pool-attenuated). fp32 accumulate.
template <int BN, int H, int WARPS_M, int WARPS_N>
__global__ void gemm_bf16_kernel(const float* __restrict__ A,
                                 const float* __restrict__ B,
                                 __nv_bfloat16* __restrict__ Cb,
                                 int M, int N, int K,
                                 const float* __restrict__ att_src,
                                 const float* __restrict__ att_dst,
                                 float* __restrict__ asrc,
                                 float* __restrict__ adst) {
    constexpr int BM = 128, BK = 16;
    constexpr int NT = WARPS_M * WARPS_N * 32;   // 256
    constexpr int WM = BM / WARPS_M;
    constexpr int WN = BN / WARPS_N;             // 64
    constexpr int MI = WM / 16;
    constexpr int NI = WN / 8;                   // 8
    __shared__ __align__(16) __nv_bfloat16 As[BM][BK + 8];
    __shared__ __align__(16) __nv_bfloat16 BsH[BK][BN + 8];
    __shared__ __align__(16) __nv_bfloat16 BsL[BK][BN + 8];

    int tid = threadIdx.x;
    int warp = tid >> 5, lane = tid & 31;
    int wm = warp / WARPS_N, wn = warp % WARPS_N;
    int row0 = blockIdx.y * BM, col0 = blockIdx.x * BN;

    float acc[MI][NI][4];
#pragma unroll
    for (int mi = 0; mi < MI; mi++)
#pragma unroll
        for (int nj = 0; nj < NI; nj++)
#pragma unroll
            for (int r = 0; r < 4; r++) acc[mi][nj][r] = 0.f;

    unsigned aAddr[MI];
#pragma unroll
    for (int mi = 0; mi < MI; mi++)
        aAddr[mi] = scvta(&As[wm * WM + mi * 16 + (lane & 7) + ((lane >> 3) & 1) * 8]
                             [(lane >> 4) * 8]);
    unsigned bAddrH[NI / 2], bAddrL[NI / 2];
#pragma unroll
    for (int np = 0; np < NI / 2; np++) {
        bAddrH[np] = scvta(&BsH[lane & 15][wn * WN + np * 16 + (lane >> 4) * 8]);
        bAddrL[np] = scvta(&BsL[lane & 15][wn * WN + np * 16 + (lane >> 4) * 8]);
    }

    for (int k0 = 0; k0 < K; k0 += BK) {
        // A tile: BM x BK fp32 -> bf16
#pragma unroll
        for (int i = 0; i < (BM * BK / 4) / NT; i++) {
            int f = tid + i * NT;
            int r = f >> 2;
            int c4 = f & 3;
            int rr = row0 + r;
            float4 v = make_float4(0.f, 0.f, 0.f, 0.f);
            if (rr < M) v = *(const float4*)&A[(size_t)rr * K + k0 + c4 * 4];
            __nv_bfloat162 p0 = __floats2bfloat162_rn(v.x, v.y);
            __nv_bfloat162 p1 = __floats2bfloat162_rn(v.z, v.w);
            unsigned u0, u1;
            memcpy(&u0, &p0, 4); memcpy(&u1, &p1, 4);
            *(uint2*)&As[r][c4 * 4] = make_uint2(u0, u1);
        }
        // B tile: BK x BN fp32 -> (hi, lo) bf16
#pragma unroll
        for (int i = 0; i < (BK * BN / 4) / NT; i++) {
            int f = tid + i * NT;
            int r = f / (BN / 4);
            int c4 = f % (BN / 4);
            float4 v = *(const float4*)&B[(size_t)(k0 + r) * N + col0 + c4 * 4];
            unsigned h0, l0, h1, l1;
            split2(v.x, v.y, h0, l0);
            split2(v.z, v.w, h1, l1);
            *(uint2*)&BsH[r][c4 * 4] = make_uint2(h0, h1);
            *(uint2*)&BsL[r][c4 * 4] = make_uint2(l0, l1);
        }
        __syncthreads();

        unsigned a[MI][4];
#pragma unroll
        for (int mi = 0; mi < MI; mi++)
            ldsm_x4(a[mi][0], a[mi][1], a[mi][2], a[mi][3], aAddr[mi]);
#pragma unroll
        for (int np = 0; np < NI / 2; np++) {
            unsigned b0, b1, b2, b3, c0, c1, c2, c3;
            ldsm_x4_t(b0, b1, b2, b3, bAddrH[np]);
            ldsm_x4_t(c0, c1, c2, c3, bAddrL[np]);
#pragma unroll
            for (int mi = 0; mi < MI; mi++) {
                mma16816(acc[mi][2 * np + 0], a[mi], b0, b1);
                mma16816(acc[mi][2 * np + 0], a[mi], c0, c1);
                mma16816(acc[mi][2 * np + 1], a[mi], b2, b3);
                mma16816(acc[mi][2 * np + 1], a[mi], c2, c3);
            }
        }
        __syncthreads();
    }

    // ---- epilogue: bf16 store + fused attention dots ----
    int g = lane >> 2, q = lane & 3;
    int head = (col0 + wn * WN) / 64;     // warp n-span = 64 = one head

#pragma unroll
    for (int mi = 0; mi < MI; mi++) {
#pragma unroll
        for (int hi = 0; hi < 2; hi++) {
            int row = row0 + wm * WM + mi * 16 + hi * 8 + g;
            bool valid = (row < M);
            float ps = 0.f, pd = 0.f;
#pragma unroll
            for (int nj = 0; nj < NI; nj++) {
                float dlo = acc[mi][nj][hi * 2 + 0];
                float dhi = acc[mi][nj][hi * 2 + 1];
                int c = col0 + wn * WN + nj * 8 + q * 2;
                ps += dlo * __ldg(&att_src[c]) + dhi * __ldg(&att_src[c + 1]);
                pd += dlo * __ldg(&att_dst[c]) + dhi * __ldg(&att_dst[c + 1]);
                if (valid) {
                    __nv_bfloat162 pv = __floats2bfloat162_rn(dlo, dhi);
                    *(__nv_bfloat162*)&Cb[(size_t)row * N + c] = pv;
                }
            }
            ps += __shfl_xor_sync(0xFFFFFFFFu, ps, 1);
            ps += __shfl_xor_sync(0xFFFFFFFFu, ps, 2);
            pd += __shfl_xor_sync(0xFFFFFFFFu, pd, 1);
            pd += __shfl_xor_sync(0xFFFFFFFFu, pd, 2);
            if (valid && q == 0) {
                atomicAdd(&asrc[row * H + head], ps);
                atomicAdd(&adst[row * H + head], pd);
            }
        }
    }
}

// ---------------------- fused GAT aggregation (bf16 gather) ------------------
template <int H, int CH>
__global__ void gat_agg_kernel(const __nv_bfloat16* __restrict__ hb,
                               const float* __restrict__ asrc,
                               const float* __restrict__ adst,
                               const float* __restrict__ bias,
                               float* __restrict__ out) {
    constexpr int PER = (H * CH) / 32;
    int node = (blockIdx.x * blockDim.x + threadIdx.x) >> 5;
    int lane = threadIdx.x & 31;
    if (node >= N_NODES) return;
    int r0 = g_rowptr[node], r1 = g_rowptr[node + 1];
    const int head = (lane * PER) / CH;

    float ad[H];
#pragma unroll
    for (int hh = 0; hh < H; hh++) ad[hh] = __ldg(&adst[node * H + hh]);

    float mx[H];
#pragma unroll
    for (int hh = 0; hh < H; hh++) {
        float v = __ldg(&asrc[node * H + hh]) + ad[hh];
        mx[hh] = v > 0.f ? v : NEG_SLOPE * v;
    }
    for (int i = r0 + lane; i < r1; i += 32) {
        int s = g_esrc[i];
#pragma unroll
        for (int hh = 0; hh < H; hh++) {
            float v = __ldg(&asrc[s * H + hh]) + ad[hh];
            v = v > 0.f ? v : NEG_SLOPE * v;
            mx[hh] = fmaxf(mx[hh], v);
        }
    }
#pragma unroll
    for (int hh = 0; hh < H; hh++)
#pragma unroll
        for (int o = 16; o; o >>= 1)
            mx[hh] = fmaxf(mx[hh], __shfl_xor_sync(0xFFFFFFFFu, mx[hh], o));

    float acc[PER];
#pragma unroll
    for (int j = 0; j < PER; j++) acc[j] = 0.f;
    float wsum = 0.f;
    float mh = mx[head];
    float adh = ad[head];

    {   // self loop
        float v = __ldg(&asrc[node * H + head]) + adh;
        v = v > 0.f ? v : NEG_SLOPE * v;
        float w = __expf(v - mh);
        wsum += w;
        const __nv_bfloat16* hp = hb + (size_t)node * (H * CH) + lane * PER;
        if constexpr (PER == 8) {
            uint4 v4 = *(const uint4*)hp;
            float2 f0 = bf2f(v4.x), f1 = bf2f(v4.y), f2 = bf2f(v4.z), f3 = bf2f(v4.w);
            acc[0] += w * f0.x; acc[1] += w * f0.y; acc[2] += w * f1.x; acc[3] += w * f1.y;
            acc[4] += w * f2.x; acc[5] += w * f2.y; acc[6] += w * f3.x; acc[7] += w * f3.y;
        } else {
            float2 f = bf2f(*(const unsigned*)hp);
            acc[0] += w * f.x; acc[1] += w * f.y;
        }
    }
    for (int i = r0; i < r1; i++) {
        int s = g_esrc[i];
        float v = __ldg(&asrc[s * H + head]) + adh;
        v = v > 0.f ? v : NEG_SLOPE * v;
        float w = __expf(v - mh);
        wsum += w;
        const __nv_bfloat16* hp = hb + (size_t)s * (H * CH) + lane * PER;
        if constexpr (PER == 8) {
            uint4 v4 = *(const uint4*)hp;
            float2 f0 = bf2f(v4.x), f1 = bf2f(v4.y), f2 = bf2f(v4.z), f3 = bf2f(v4.w);
            acc[0] += w * f0.x; acc[1] += w * f0.y; acc[2] += w * f1.x; acc[3] += w * f1.y;
            acc[4] += w * f2.x; acc[5] += w * f2.y; acc[6] += w * f3.x; acc[7] += w * f3.y;
        } else {
            float2 f = bf2f(*(const unsigned*)hp);
            acc[0] += w * f.x; acc[1] += w * f.y;
        }
    }

    float inv = 1.f / (wsum + 1e-16f);
    float* op = out + (size_t)node * (H * CH) + lane * PER;
#pragma unroll
    for (int j = 0; j < PER; j++) {
        float v = acc[j] * inv + __ldg(&bias[lane * PER + j]);
        op[j] = v > 0.f ? v : expm1f(v);
    }
}

// ---------------------- graph mean-pool accumulation -------------------------
__global__ void pool_kernel(const void* __restrict__ batch,
                            const float* __restrict__ feat) {
    int i = blockIdx.x * blockDim.x + threadIdx.x;
    if (i >= N_NODES * C2) return;
    int n = i / C2;
    int c = i - n * C2;
    int g = idx_at(batch, n);
    atomicAdd(&g_pool[g * C2 + c], feat[i]);
    if (c == 0) atomicAdd(&g_cnt[g], 1);
}

// ---------------------- final MLP (tiny) --------------------------------------
__global__ void mlp_kernel(const float* __restrict__ w1, const float* __restrict__ bb1,
                           const float* __restrict__ w2, const float* __restrict__ bb2,
                           float* __restrict__ outp) {
    __shared__ float ps[G_GRAPHS * C2];
    __shared__ float zs[G_GRAPHS * 128];
    for (int i = threadIdx.x; i < G_GRAPHS * C2; i += blockDim.x) {
        int g = i / C2;
        float c = (float)g_cnt[g];
        ps[i] = g_pool[i] / fmaxf(c, 1.f);
    }
    __syncthreads();
    int j = threadIdx.x;
    for (int g = 0; g < G_GRAPHS; g++) {
        float acc = bb1[j];
#pragma unroll 8
        for (int c = 0; c < C2; c++) acc += ps[g * C2 + c] * w1[c * 128 + j];
        zs[g * 128 + j] = fmaxf(acc, 0.f);
    }
    __syncthreads();
    if (threadIdx.x < G_GRAPHS) {
        int g = threadIdx.x;
        float acc = bb2[0];
#pragma unroll 8
        for (int k = 0; k < 128; k++) acc += zs[g * 128 + k] * w2[k];
        outp[g] = acc;
    }
}

// =============================================================================
extern "C" void kernel_launch(void* const* d_in, const int* in_sizes, int n_in,
                              void* d_out, int out_size) {
    const float *x = nullptr, *W1 = nullptr, *as1 = nullptr, *ad1 = nullptr, *b1 = nullptr;
    const float *W2 = nullptr, *as2 = nullptr, *ad2 = nullptr, *b2 = nullptr;
    const float *l1w = nullptr, *l1b = nullptr, *l2w = nullptr, *l2b = nullptr;
    const void *ei = nullptr, *batch = nullptr;
    int n256 = 0, n64 = 0, n128 = 0;
    for (int i = 0; i < n_in; i++) {
        const void* p = d_in[i];
        switch (in_sizes[i]) {
            case 6400000: x = (const float*)p; break;
            case 1600000: ei = p; break;
            case 50000:   batch = p; break;
            case 32768:   W1 = (const float*)p; break;
            case 16384:   W2 = (const float*)p; break;
            case 8192:    l1w = (const float*)p; break;
            case 1:       l2b = (const float*)p; break;
            case 256:
                if (n256 == 0) as1 = (const float*)p;
                else if (n256 == 1) ad1 = (const float*)p;
                else b1 = (const float*)p;
                n256++;
                break;
            case 64:
                if (n64 == 0) as2 = (const float*)p;
                else if (n64 == 1) ad2 = (const float*)p;
                else b2 = (const float*)p;
                n64++;
                break;
            case 128:
                if (n128 == 0) l1b = (const float*)p;
                else l2w = (const float*)p;
                n128++;
                break;
            default: break;
        }
    }
    float* outp = (float*)d_out;

    __nv_bfloat16* h1b; cudaGetSymbolAddress((void**)&h1b, g_h1b);
    __nv_bfloat16* h2b; cudaGetSymbolAddress((void**)&h2b, g_h2b);
    float* out1;  cudaGetSymbolAddress((void**)&out1, g_out1);
    float* out2;  cudaGetSymbolAddress((void**)&out2, g_out2);
    float* asr1;  cudaGetSymbolAddress((void**)&asr1, g_asrc1);
    float* ads1;  cudaGetSymbolAddress((void**)&ads1, g_adst1);
    float* asr2;  cudaGetSymbolAddress((void**)&asr2, g_asrc2);
    float* ads2;  cudaGetSymbolAddress((void**)&ads2, g_adst2);

    const int BT = 256;
    int eb = (E_EDGES + BT - 1) / BT;

    // launch order keeps gemm1 at launch index 3 (ncu profiles it)
    clear_kernel<<<512, BT>>>(ei);                    // 0
    count_kernel<<<eb, BT>>>(ei);                     // 1
    scan1_kernel<<<NB_SCAN, 256>>>();                 // 2
    {                                                 // 3: gemm1 + fused alpha1
        dim3 grid(C1 / 128, (N_NODES + 127) / 128);
        gemm_bf16_kernel<128, H1, 4, 2><<<grid, 256>>>(x, W1, h1b, N_NODES, C1, 128,
                                                       as1, ad1, asr1, ads1);
    }
    scan2_kernel<<<1, 256>>>();                       // 4
    scan3_kernel<<<NB_SCAN, 256>>>();                 // 5
    fill_kernel<<<eb, BT>>>(ei);                      // 6

    int blocks = (N_NODES * 32 + BT - 1) / BT;
    gat_agg_kernel<H1, 64><<<blocks, BT>>>(h1b, asr1, ads1, b1, out1);  // 7
    {                                                 // 8: gemm2 + fused alpha2
        dim3 grid(1, (N_NODES + 127) / 128);
        gemm_bf16_kernel<64, 1, 8, 1><<<grid, 256>>>(out1, W2, h2b, N_NODES, C2, 256,
                                                     as2, ad2, asr2, ads2);
    }
    gat_agg_kernel<1, 64><<<blocks, BT>>>(h2b, asr2, ads2, b2, out2);   // 9

    int n = N_NODES * C2;
    pool_kernel<<<(n + BT - 1) / BT, BT>>>(batch, out2);                // 10
    mlp_kernel<<<1, 128>>>(l1w, l1b, l2w, l2b, outp);                   // 11
}

// round 10
// speedup vs baseline: 3.8255x; 1.0763x over previous
#include <cuda_runtime.h>
#include <cuda_bf16.h>
#include <cstdint>

// Problem constants (fixed by reference)
#define N_NODES 50000
#define E_EDGES 800000
#define G_GRAPHS 64
#define C1 256           // HEADS*HID after layer 1
#define C2 64            // HID after layer 2
#define H1 4             // heads layer 1
#define IN_C 128
#define NEG_SLOPE 0.2f
#define NB_SCAN ((N_NODES + 255) / 256)

// ------------------------- device scratch (no allocs allowed) ---------------
__device__ __nv_bfloat16 g_xb[N_NODES * IN_C];    // bf16 copy of x
__device__ __nv_bfloat16 g_h1b[N_NODES * C1];     // bf16 x@W1 (gather src)
__device__ __nv_bfloat16 g_out1b[N_NODES * C1];   // bf16 layer-1 output (gemm2 A)
__device__ __nv_bfloat16 g_h2b[N_NODES * C2];     // bf16 out1@W2
__device__ float g_out2[N_NODES * C2];
__device__ __nv_bfloat16 g_w1h[IN_C * C1], g_w1l[IN_C * C1];   // W1 hi/lo split
__device__ __nv_bfloat16 g_w2h[C1 * C2],  g_w2l[C1 * C2];      // W2 hi/lo split
__device__ float g_asrc1[N_NODES * H1];
__device__ float g_adst1[N_NODES * H1];
__device__ float g_asrc2[N_NODES];
__device__ float g_adst2[N_NODES];
__device__ float g_pool[G_GRAPHS * C2];
__device__ int   g_cnt[G_GRAPHS];
__device__ int   g_is64;
// CSR by destination
__device__ int g_deg[N_NODES];
__device__ int g_fill[N_NODES];
__device__ int g_rowptr[N_NODES + 1];
__device__ int g_esrc[E_EDGES];
__device__ int g_bsum[NB_SCAN];

// ---------------------- helpers ---------------------------------------------
__device__ __forceinline__ int idx_at(const void* __restrict__ p, int i) {
    if (g_is64) return (int)((const long long*)p)[i];
    return ((const int*)p)[i];
}
__device__ __forceinline__ float2 bf2f(unsigned v) {
    return __bfloat1622float2(*reinterpret_cast<const __nv_bfloat162*>(&v));
}
__device__ __forceinline__ unsigned scvta(const void* p) {
    return (unsigned)__cvta_generic_to_shared(p);
}
__device__ __forceinline__ void ldsm_x4(unsigned& r0, unsigned& r1, unsigned& r2,
                                        unsigned& r3, unsigned addr) {
    asm volatile("ldmatrix.sync.aligned.m8n8.x4.shared.b16 {%0,%1,%2,%3}, [%4];"
                 : "=r"(r0), "=r"(r1), "=r"(r2), "=r"(r3) : "r"(addr) : "memory");
}
__device__ __forceinline__ void ldsm_x4_t(unsigned& r0, unsigned& r1, unsigned& r2,
                                          unsigned& r3, unsigned addr) {
    asm volatile("ldmatrix.sync.aligned.m8n8.x4.trans.shared.b16 {%0,%1,%2,%3}, [%4];"
                 : "=r"(r0), "=r"(r1), "=r"(r2), "=r"(r3) : "r"(addr) : "memory");
}
__device__ __forceinline__ void mma16816(float* c, const unsigned* a,
                                         unsigned b0, unsigned b1) {
    asm volatile(
        "mma.sync.aligned.m16n8k16.row.col.f32.bf16.bf16.f32 "
        "{%0,%1,%2,%3}, {%4,%5,%6,%7}, {%8,%9}, {%0,%1,%2,%3};"
        : "+f"(c[0]), "+f"(c[1]), "+f"(c[2]), "+f"(c[3])
        : "r"(a[0]), "r"(a[1]), "r"(a[2]), "r"(a[3]), "r"(b0), "r"(b1));
}

// ---------------------- clear + dtype detection ------------------------------
__global__ void clear_kernel(const void* __restrict__ ei) {
    int stride = gridDim.x * blockDim.x;
    int gid = blockIdx.x * blockDim.x + threadIdx.x;
    if (gid == 0) {
        const long long* p = (const long long*)ei;
        int ok64 = 1;
        for (int i = 0; i < 64; i++) {
            long long v = p[i];
            if (v < 0 || v >= N_NODES) { ok64 = 0; break; }
        }
        g_is64 = ok64;
    }
    for (int i = gid; i < N_NODES; i += stride) { g_deg[i] = 0; g_fill[i] = 0; }
    for (int i = gid; i < N_NODES * H1; i += stride) { g_asrc1[i] = 0.f; g_adst1[i] = 0.f; }
    for (int i = gid; i < N_NODES; i += stride) { g_asrc2[i] = 0.f; g_adst2[i] = 0.f; }
    for (int i = gid; i < G_GRAPHS * C2; i += stride) g_pool[i] = 0.f;
    for (int i = gid; i < G_GRAPHS; i += stride) g_cnt[i] = 0;
}

// ---------------------- prep: x -> bf16, W1/W2 -> hi/lo split -----------------
__global__ void prep_kernel(const float* __restrict__ x,
                            const float* __restrict__ W1,
                            const float* __restrict__ W2) {
    int stride = gridDim.x * blockDim.x;
    int gid = blockIdx.x * blockDim.x + threadIdx.x;
    // x: vectorized float4 -> bf16x4
    for (int i = gid; i < (N_NODES * IN_C) / 4; i += stride) {
        float4 v = *(const float4*)&x[i * 4];
        __nv_bfloat162 p0 = __floats2bfloat162_rn(v.x, v.y);
        __nv_bfloat162 p1 = __floats2bfloat162_rn(v.z, v.w);
        unsigned u0, u1;
        memcpy(&u0, &p0, 4); memcpy(&u1, &p1, 4);
        *(uint2*)&g_xb[i * 4] = make_uint2(u0, u1);
    }
    // W1 split
    for (int i = gid; i < IN_C * C1; i += stride) {
        float w = W1[i];
        __nv_bfloat16 h = __float2bfloat16_rn(w);
        g_w1h[i] = h;
        g_w1l[i] = __float2bfloat16_rn(w - __bfloat162float(h));
    }
    // W2 split
    for (int i = gid; i < C1 * C2; i += stride) {
        float w = W2[i];
        __nv_bfloat16 h = __float2bfloat16_rn(w);
        g_w2h[i] = h;
        g_w2l[i] = __float2bfloat16_rn(w - __bfloat162float(h));
    }
}

// ---------------------- CSR build --------------------------------------------
__global__ void count_kernel(const void* __restrict__ ei) {
    int e = blockIdx.x * blockDim.x + threadIdx.x;
    if (e >= E_EDGES) return;
    int d = idx_at(ei, E_EDGES + e);
    atomicAdd(&g_deg[d], 1);
}

__global__ void scan1_kernel() {
    __shared__ int sh[256];
    int i = blockIdx.x * 256 + threadIdx.x;
    sh[threadIdx.x] = (i < N_NODES) ? g_deg[i] : 0;
    __syncthreads();
    for (int off = 128; off; off >>= 1) {
        if (threadIdx.x < off) sh[threadIdx.x] += sh[threadIdx.x + off];
        __syncthreads();
    }
    if (threadIdx.x == 0) g_bsum[blockIdx.x] = sh[0];
}
__global__ void scan2_kernel() {
    __shared__ int sh[256];
    int t = threadIdx.x;
    sh[t] = (t < NB_SCAN) ? g_bsum[t] : 0;
    __syncthreads();
    for (int off = 1; off < 256; off <<= 1) {
        int v = (t >= off) ? sh[t - off] : 0;
        __syncthreads();
        sh[t] += v;
        __syncthreads();
    }
    if (t < NB_SCAN) g_bsum[t] = sh[t];
}
__global__ void scan3_kernel() {
    __shared__ int sh[256];
    int t = threadIdx.x;
    int i = blockIdx.x * 256 + t;
    int v = (i < N_NODES) ? g_deg[i] : 0;
    sh[t] = v;
    __syncthreads();
    for (int off = 1; off < 256; off <<= 1) {
        int u = (t >= off) ? sh[t - off] : 0;
        __syncthreads();
        sh[t] += u;
        __syncthreads();
    }
    int base = blockIdx.x ? g_bsum[blockIdx.x - 1] : 0;
    if (i < N_NODES) g_rowptr[i] = base + sh[t] - v;
    if (i == N_NODES - 1) g_rowptr[N_NODES] = base + sh[t];
}

__global__ void fill_kernel(const void* __restrict__ ei) {
    int e = blockIdx.x * blockDim.x + threadIdx.x;
    if (e >= E_EDGES) return;
    int s = idx_at(ei, e);
    int d = idx_at(ei, E_EDGES + e);
    int slot = g_rowptr[d] + atomicAdd(&g_fill[d], 1);
    g_esrc[slot] = s;
}

// ---------------------- bf16 tensor-core GEMM (preconverted) + fused alpha ---
// C = A @ (Bh + Bl); A, Bh, Bl all bf16 in gmem (converted/split once by
// prep/agg kernels). fp32 accumulate; mainloop is pure copies + ldmatrix + mma.
template <int BN, int H, int WARPS_M, int WARPS_N>
__global__ void gemm_bf16_kernel(const __nv_bfloat16* __restrict__ A,
                                 const __nv_bfloat16* __restrict__ Bh,
                                 const __nv_bfloat16* __restrict__ Bl,
                                 __nv_bfloat16* __restrict__ Cb,
                                 int M, int N, int K,
                                 const float* __restrict__ att_src,
                                 const float* __restrict__ att_dst,
                                 float* __restrict__ asrc,
                                 float* __restrict__ adst) {
    constexpr int BM = 128, BK = 16;
    constexpr int NT = WARPS_M * WARPS_N * 32;   // 256
    constexpr int WM = BM / WARPS_M;
    constexpr int WN = BN / WARPS_N;             // 64
    constexpr int MI = WM / 16;
    constexpr int NI = WN / 8;                   // 8
    __shared__ __align__(16) __nv_bfloat16 As[BM][BK + 8];
    __shared__ __align__(16) __nv_bfloat16 BsH[BK][BN + 8];
    __shared__ __align__(16) __nv_bfloat16 BsL[BK][BN + 8];

    int tid = threadIdx.x;
    int warp = tid >> 5, lane = tid & 31;
    int wm = warp / WARPS_N, wn = warp % WARPS_N;
    int row0 = blockIdx.y * BM, col0 = blockIdx.x * BN;

    float acc[MI][NI][4];
#pragma unroll
    for (int mi = 0; mi < MI; mi++)
#pragma unroll
        for (int nj = 0; nj < NI; nj++)
#pragma unroll
            for (int r = 0; r < 4; r++) acc[mi][nj][r] = 0.f;

    unsigned aAddr[MI];
#pragma unroll
    for (int mi = 0; mi < MI; mi++)
        aAddr[mi] = scvta(&As[wm * WM + mi * 16 + (lane & 7) + ((lane >> 3) & 1) * 8]
                             [(lane >> 4) * 8]);
    unsigned bAddrH[NI / 2], bAddrL[NI / 2];
#pragma unroll
    for (int np = 0; np < NI / 2; np++) {
        bAddrH[np] = scvta(&BsH[lane & 15][wn * WN + np * 16 + (lane >> 4) * 8]);
        bAddrL[np] = scvta(&BsL[lane & 15][wn * WN + np * 16 + (lane >> 4) * 8]);
    }

    for (int k0 = 0; k0 < K; k0 += BK) {
        // A tile: BM x BK bf16, one uint4 (8 bf16) per thread
        {
            int r = tid >> 1;
            int half = tid & 1;
            int rr = row0 + r;
            uint4 v = make_uint4(0, 0, 0, 0);
            if (rr < M) v = *(const uint4*)&A[(size_t)rr * K + k0 + half * 8];
            *(uint4*)&As[r][half * 8] = v;
        }
        // B tiles: BK x BN bf16 hi+lo
#pragma unroll
        for (int f = tid; f < BK * BN / 8; f += NT) {
            int r = f / (BN / 8);
            int c8 = f % (BN / 8);
            size_t off = (size_t)(k0 + r) * N + col0 + c8 * 8;
            *(uint4*)&BsH[r][c8 * 8] = *(const uint4*)&Bh[off];
            *(uint4*)&BsL[r][c8 * 8] = *(const uint4*)&Bl[off];
        }
        __syncthreads();

        unsigned a[MI][4];
#pragma unroll
        for (int mi = 0; mi < MI; mi++)
            ldsm_x4(a[mi][0], a[mi][1], a[mi][2], a[mi][3], aAddr[mi]);
#pragma unroll
        for (int np = 0; np < NI / 2; np++) {
            unsigned b0, b1, b2, b3, c0, c1, c2, c3;
            ldsm_x4_t(b0, b1, b2, b3, bAddrH[np]);
            ldsm_x4_t(c0, c1, c2, c3, bAddrL[np]);
#pragma unroll
            for (int mi = 0; mi < MI; mi++) {
                mma16816(acc[mi][2 * np + 0], a[mi], b0, b1);
                mma16816(acc[mi][2 * np + 0], a[mi], c0, c1);
                mma16816(acc[mi][2 * np + 1], a[mi], b2, b3);
                mma16816(acc[mi][2 * np + 1], a[mi], c2, c3);
            }
        }
        __syncthreads();
    }

    // ---- epilogue: bf16 store + fused attention dots ----
    int g = lane >> 2, q = lane & 3;
    int head = (col0 + wn * WN) / 64;     // warp n-span = 64 = one head

#pragma unroll
    for (int mi = 0; mi < MI; mi++) {
#pragma unroll
        for (int hi = 0; hi < 2; hi++) {
            int row = row0 + wm * WM + mi * 16 + hi * 8 + g;
            bool valid = (row < M);
            float ps = 0.f, pd = 0.f;
#pragma unroll
            for (int nj = 0; nj < NI; nj++) {
                float dlo = acc[mi][nj][hi * 2 + 0];
                float dhi = acc[mi][nj][hi * 2 + 1];
                int c = col0 + wn * WN + nj * 8 + q * 2;
                ps += dlo * __ldg(&att_src[c]) + dhi * __ldg(&att_src[c + 1]);
                pd += dlo * __ldg(&att_dst[c]) + dhi * __ldg(&att_dst[c + 1]);
                if (valid) {
                    __nv_bfloat162 pv = __floats2bfloat162_rn(dlo, dhi);
                    *(__nv_bfloat162*)&Cb[(size_t)row * N + c] = pv;
                }
            }
            ps += __shfl_xor_sync(0xFFFFFFFFu, ps, 1);
            ps += __shfl_xor_sync(0xFFFFFFFFu, ps, 2);
            pd += __shfl_xor_sync(0xFFFFFFFFu, pd, 1);
            pd += __shfl_xor_sync(0xFFFFFFFFu, pd, 2);
            if (valid && q == 0) {
                atomicAdd(&asrc[row * H + head], ps);
                atomicAdd(&adst[row * H + head], pd);
            }
        }
    }
}

// ---------------------- fused GAT aggregation (bf16 gather) ------------------
// OUT_BF16: layer-1 writes bf16 (feeds gemm2's bf16 A operand directly —
// identical rounding to the fp32->smem-bf16 path it replaces).
template <int H, int CH, bool OUT_BF16>
__global__ void gat_agg_kernel(const __nv_bfloat16* __restrict__ hb,
                               const float* __restrict__ asrc,
                               const float* __restrict__ adst,
                               const float* __restrict__ bias,
                               void* __restrict__ outv) {
    constexpr int PER = (H * CH) / 32;
    int node = (blockIdx.x * blockDim.x + threadIdx.x) >> 5;
    int lane = threadIdx.x & 31;
    if (node >= N_NODES) return;
    int r0 = g_rowptr[node], r1 = g_rowptr[node + 1];
    const int head = (lane * PER) / CH;

    float ad[H];
#pragma unroll
    for (int hh = 0; hh < H; hh++) ad[hh] = __ldg(&adst[node * H + hh]);

    float mx[H];
#pragma unroll
    for (int hh = 0; hh < H; hh++) {
        float v = __ldg(&asrc[node * H + hh]) + ad[hh];
        mx[hh] = v > 0.f ? v : NEG_SLOPE * v;
    }
    for (int i = r0 + lane; i < r1; i += 32) {
        int s = g_esrc[i];
#pragma unroll
        for (int hh = 0; hh < H; hh++) {
            float v = __ldg(&asrc[s * H + hh]) + ad[hh];
            v = v > 0.f ? v : NEG_SLOPE * v;
            mx[hh] = fmaxf(mx[hh], v);
        }
    }
#pragma unroll
    for (int hh = 0; hh < H; hh++)
#pragma unroll
        for (int o = 16; o; o >>= 1)
            mx[hh] = fmaxf(mx[hh], __shfl_xor_sync(0xFFFFFFFFu, mx[hh], o));

    float acc[PER];
#pragma unroll
    for (int j = 0; j < PER; j++) acc[j] = 0.f;
    float wsum = 0.f;
    float mh = mx[head];
    float adh = ad[head];

    {   // self loop
        float v = __ldg(&asrc[node * H + head]) + adh;
        v = v > 0.f ? v : NEG_SLOPE * v;
        float w = __expf(v - mh);
        wsum += w;
        const __nv_bfloat16* hp = hb + (size_t)node * (H * CH) + lane * PER;
        if constexpr (PER == 8) {
            uint4 v4 = *(const uint4*)hp;
            float2 f0 = bf2f(v4.x), f1 = bf2f(v4.y), f2 = bf2f(v4.z), f3 = bf2f(v4.w);
            acc[0] += w * f0.x; acc[1] += w * f0.y; acc[2] += w * f1.x; acc[3] += w * f1.y;
            acc[4] += w * f2.x; acc[5] += w * f2.y; acc[6] += w * f3.x; acc[7] += w * f3.y;
        } else {
            float2 f = bf2f(*(const unsigned*)hp);
            acc[0] += w * f.x; acc[1] += w * f.y;
        }
    }
    for (int i = r0; i < r1; i++) {
        int s = g_esrc[i];
        float v = __ldg(&asrc[s * H + head]) + adh;
        v = v > 0.f ? v : NEG_SLOPE * v;
        float w = __expf(v - mh);
        wsum += w;
        const __nv_bfloat16* hp = hb + (size_t)s * (H * CH) + lane * PER;
        if constexpr (PER == 8) {
            uint4 v4 = *(const uint4*)hp;
            float2 f0 = bf2f(v4.x), f1 = bf2f(v4.y), f2 = bf2f(v4.z), f3 = bf2f(v4.w);
            acc[0] += w * f0.x; acc[1] += w * f0.y; acc[2] += w * f1.x; acc[3] += w * f1.y;
            acc[4] += w * f2.x; acc[5] += w * f2.y; acc[6] += w * f3.x; acc[7] += w * f3.y;
        } else {
            float2 f = bf2f(*(const unsigned*)hp);
            acc[0] += w * f.x; acc[1] += w * f.y;
        }
    }

    float inv = 1.f / (wsum + 1e-16f);
    float vals[PER];
#pragma unroll
    for (int j = 0; j < PER; j++) {
        float v = acc[j] * inv + __ldg(&bias[lane * PER + j]);
        vals[j] = v > 0.f ? v : expm1f(v);
    }
    if constexpr (OUT_BF16) {
        __nv_bfloat16* op = (__nv_bfloat16*)outv + (size_t)node * (H * CH) + lane * PER;
        if constexpr (PER == 8) {
            __nv_bfloat162 p0 = __floats2bfloat162_rn(vals[0], vals[1]);
            __nv_bfloat162 p1 = __floats2bfloat162_rn(vals[2], vals[3]);
            __nv_bfloat162 p2 = __floats2bfloat162_rn(vals[4], vals[5]);
            __nv_bfloat162 p3 = __floats2bfloat162_rn(vals[6], vals[7]);
            unsigned u0, u1, u2, u3;
            memcpy(&u0, &p0, 4); memcpy(&u1, &p1, 4);
            memcpy(&u2, &p2, 4); memcpy(&u3, &p3, 4);
            *(uint4*)op = make_uint4(u0, u1, u2, u3);
        } else {
#pragma unroll
            for (int j = 0; j < PER; j++) op[j] = __float2bfloat16_rn(vals[j]);
        }
    } else {
        float* op = (float*)outv + (size_t)node * (H * CH) + lane * PER;
#pragma unroll
        for (int j = 0; j < PER; j++) op[j] = vals[j];
    }
}

// ---------------------- graph mean-pool accumulation -------------------------
__global__ void pool_kernel(const void* __restrict__ batch,
                            const float* __restrict__ feat) {
    int i = blockIdx.x * blockDim.x + threadIdx.x;
    if (i >= N_NODES * C2) return;
    int n = i / C2;
    int c = i - n * C2;
    int g = idx_at(batch, n);
    atomicAdd(&g_pool[g * C2 + c], feat[i]);
    if (c == 0) atomicAdd(&g_cnt[g], 1);
}

// ---------------------- final MLP (tiny) --------------------------------------
__global__ void mlp_kernel(const float* __restrict__ w1, const float* __restrict__ bb1,
                           const float* __restrict__ w2, const float* __restrict__ bb2,
                           float* __restrict__ outp) {
    __shared__ float ps[G_GRAPHS * C2];
    __shared__ float zs[G_GRAPHS * 128];
    for (int i = threadIdx.x; i < G_GRAPHS * C2; i += blockDim.x) {
        int g = i / C2;
        float c = (float)g_cnt[g];
        ps[i] = g_pool[i] / fmaxf(c, 1.f);
    }
    __syncthreads();
    int j = threadIdx.x;
    for (int g = 0; g < G_GRAPHS; g++) {
        float acc = bb1[j];
#pragma unroll 8
        for (int c = 0; c < C2; c++) acc += ps[g * C2 + c] * w1[c * 128 + j];
        zs[g * 128 + j] = fmaxf(acc, 0.f);
    }
    __syncthreads();
    if (threadIdx.x < G_GRAPHS) {
        int g = threadIdx.x;
        float acc = bb2[0];
#pragma unroll 8
        for (int k = 0; k < 128; k++) acc += zs[g * 128 + k] * w2[k];
        outp[g] = acc;
    }
}

// =============================================================================
extern "C" void kernel_launch(void* const* d_in, const int* in_sizes, int n_in,
                              void* d_out, int out_size) {
    const float *x = nullptr, *W1 = nullptr, *as1 = nullptr, *ad1 = nullptr, *b1 = nullptr;
    const float *W2 = nullptr, *as2 = nullptr, *ad2 = nullptr, *b2 = nullptr;
    const float *l1w = nullptr, *l1b = nullptr, *l2w = nullptr, *l2b = nullptr;
    const void *ei = nullptr, *batch = nullptr;
    int n256 = 0, n64 = 0, n128 = 0;
    for (int i = 0; i < n_in; i++) {
        const void* p = d_in[i];
        switch (in_sizes[i]) {
            case 6400000: x = (const float*)p; break;
            case 1600000: ei = p; break;
            case 50000:   batch = p; break;
            case 32768:   W1 = (const float*)p; break;
            case 16384:   W2 = (const float*)p; break;
            case 8192:    l1w = (const float*)p; break;
            case 1:       l2b = (const float*)p; break;
            case 256:
                if (n256 == 0) as1 = (const float*)p;
                else if (n256 == 1) ad1 = (const float*)p;
                else b1 = (const float*)p;
                n256++;
                break;
            case 64:
                if (n64 == 0) as2 = (const float*)p;
                else if (n64 == 1) ad2 = (const float*)p;
                else b2 = (const float*)p;
                n64++;
                break;
            case 128:
                if (n128 == 0) l1b = (const float*)p;
                else l2w = (const float*)p;
                n128++;
                break;
            default: break;
        }
    }
    float* outp = (float*)d_out;

    __nv_bfloat16 *xb, *h1b, *out1b, *h2b, *w1h, *w1l, *w2h, *w2l;
    cudaGetSymbolAddress((void**)&xb, g_xb);
    cudaGetSymbolAddress((void**)&h1b, g_h1b);
    cudaGetSymbolAddress((void**)&out1b, g_out1b);
    cudaGetSymbolAddress((void**)&h2b, g_h2b);
    cudaGetSymbolAddress((void**)&w1h, g_w1h);
    cudaGetSymbolAddress((void**)&w1l, g_w1l);
    cudaGetSymbolAddress((void**)&w2h, g_w2h);
    cudaGetSymbolAddress((void**)&w2l, g_w2l);
    float *out2, *asr1, *ads1, *asr2, *ads2;
    cudaGetSymbolAddress((void**)&out2, g_out2);
    cudaGetSymbolAddress((void**)&asr1, g_asrc1);
    cudaGetSymbolAddress((void**)&ads1, g_adst1);
    cudaGetSymbolAddress((void**)&asr2, g_asrc2);
    cudaGetSymbolAddress((void**)&ads2, g_adst2);

    const int BT = 256;
    int eb = (E_EDGES + BT - 1) / BT;

    // launch order keeps gemm1 at launch index 3 (ncu profiles it)
    clear_kernel<<<512, BT>>>(ei);                    // 0
    prep_kernel<<<1024, BT>>>(x, W1, W2);             // 1
    count_kernel<<<eb, BT>>>(ei);                     // 2
    {                                                 // 3: gemm1 + fused alpha1
        dim3 grid(C1 / 128, (N_NODES + 127) / 128);
        gemm_bf16_kernel<128, H1, 4, 2><<<grid, 256>>>(xb, w1h, w1l, h1b,
                                                       N_NODES, C1, IN_C,
                                                       as1, ad1, asr1, ads1);
    }
    scan1_kernel<<<NB_SCAN, 256>>>();                 // 4
    scan2_kernel<<<1, 256>>>();                       // 5
    scan3_kernel<<<NB_SCAN, 256>>>();                 // 6
    fill_kernel<<<eb, BT>>>(ei);                      // 7

    int blocks = (N_NODES * 32 + BT - 1) / BT;
    gat_agg_kernel<H1, 64, true><<<blocks, BT>>>(h1b, asr1, ads1, b1, out1b);  // 8
    {                                                 // 9: gemm2 + fused alpha2
        dim3 grid(1, (N_NODES + 127) / 128);
        gemm_bf16_kernel<64, 1, 8, 1><<<grid, 256>>>(out1b, w2h, w2l, h2b,
                                                     N_NODES, C2, C1,
                                                     as2, ad2, asr2, ads2);
    }
    gat_agg_kernel<1, 64, false><<<blocks, BT>>>(h2b, asr2, ads2, b2, out2);   // 10

    int n = N_NODES * C2;
    pool_kernel<<<(n + BT - 1) / BT, BT>>>(batch, out2);                // 11
    mlp_kernel<<<1, 128>>>(l1w, l1b, l2w, l2b, outp);                   // 12
}